// round 7
// baseline (speedup 1.0000x reference)
#include <cuda_runtime.h>
#include <cstdint>

#define H   128
#define XD  64
#define ED  16
#define NMAX 50000
#define EMAX 640000
#define GPMAX 512
#define BN_EPS 1e-5f

// ---------------- scratch (static device globals; no allocation) ----------------
__device__ __align__(16) float g_h  [(size_t)NMAX * H];
__device__ __align__(16) float g_t  [(size_t)NMAX * H];
__device__ __align__(16) float g_h1 [(size_t)NMAX * H];
__device__ __align__(16) float g_pooled[GPMAX * H];
__device__ __align__(16) float g_colsum[H];
__device__ __align__(16) float g_colsumsq[H];
__device__ __align__(16) float g_scale[H];
__device__ __align__(16) float g_shift[H];
// CSR sort scratch
__device__ __align__(16) float g_eas [(size_t)EMAX * ED];  // edge_attr permuted to dst-sorted order
__device__ int   g_ssrc[EMAX];
__device__ int   g_cnt [NMAX];
__device__ int   g_row [NMAX + 1];
__device__ int   g_ofs [NMAX];

// ---------------- helpers ----------------
__device__ __forceinline__ void red_add_v4(float* addr, float4 v) {
    asm volatile("red.global.add.v4.f32 [%0], {%1,%2,%3,%4};"
                 :: "l"(addr), "f"(v.x), "f"(v.y), "f"(v.z), "f"(v.w)
                 : "memory");
}

// ---------------- CSR build: histogram -> scan -> scatter ----------------
__global__ void hist_kernel(const int* __restrict__ ei, int* __restrict__ cnt, int E)
{
    int e = blockIdx.x * blockDim.x + threadIdx.x;
    if (e < E) atomicAdd(&cnt[__ldg(ei + E + e)], 1);
}

__global__ void prefix_kernel(const int* __restrict__ cnt, int* __restrict__ row_ptr,
                              int* __restrict__ ofs, int N, int E)
{
    __shared__ int ssum[1024];
    int tid = threadIdx.x;
    int per = (N + 1023) >> 10;
    int start = tid * per;
    int end = min(start + per, N);
    int s = 0;
    for (int i = start; i < end; i++) s += cnt[i];
    ssum[tid] = s;
    __syncthreads();
    // Hillis-Steele inclusive scan over 1024 partials
    #pragma unroll
    for (int off = 1; off < 1024; off <<= 1) {
        int v = (tid >= off) ? ssum[tid - off] : 0;
        __syncthreads();
        ssum[tid] += v;
        __syncthreads();
    }
    int run = (tid > 0) ? ssum[tid - 1] : 0;
    for (int i = start; i < end; i++) {
        row_ptr[i] = run;
        ofs[i] = run;
        run += cnt[i];
    }
    if (tid == 0) row_ptr[N] = E;
}

__global__ void scatter_kernel(const int* __restrict__ ei, const float* __restrict__ ea,
                               int* __restrict__ ofs, int* __restrict__ ssrc,
                               float* __restrict__ eas, int E)
{
    int e = blockIdx.x * blockDim.x + threadIdx.x;
    if (e >= E) return;
    int dst = __ldg(ei + E + e);
    int pos = atomicAdd(&ofs[dst], 1);
    ssrc[pos] = __ldg(ei + e);
    const float4* s = (const float4*)(ea + (size_t)e * ED);
    float4* d = (float4*)(eas + (size_t)pos * ED);
    d[0] = __ldg(s + 0);
    d[1] = __ldg(s + 1);
    d[2] = __ldg(s + 2);
    d[3] = __ldg(s + 3);
}

// ------- aggregation: t[n] = h[n] + sum_{e: dst=n} relu(h[src_e] + ea_e @ Ew + Eb) ------
// one warp per node, lane owns 4 features; edge data read sequentially (dst-sorted)
__global__ void __launch_bounds__(256) aggr_kernel(
    const float* __restrict__ h, float* __restrict__ t,
    const float* __restrict__ eas, const int* __restrict__ ssrc,
    const float* __restrict__ eW, const float* __restrict__ eb,
    const int* __restrict__ row_ptr, int N,
    float* __restrict__ cs, float* __restrict__ cq)
{
    __shared__ __align__(16) float Ws[ED * H];
    __shared__ __align__(16) float ebs[H];
    for (int i = threadIdx.x; i < ED * H; i += blockDim.x) Ws[i] = eW[i];
    if (threadIdx.x < H) ebs[threadIdx.x] = eb[threadIdx.x];
    __syncthreads();
    if (blockIdx.x == 0 && threadIdx.x < H) { cs[threadIdx.x] = 0.f; cq[threadIdx.x] = 0.f; }

    const int lane = threadIdx.x & 31;
    const int f = lane * 4;
    int n = (blockIdx.x * blockDim.x + threadIdx.x) >> 5;
    if (n >= N) return;

    int beg = __ldg(row_ptr + n);
    int end = __ldg(row_ptr + n + 1);
    float4 acc = *(const float4*)(h + (size_t)n * H + f);   // self term (eps=0)
    const float4 bias4 = *(const float4*)(ebs + f);

    for (int pos = beg; pos < end; pos++) {
        int src = __ldg(ssrc + pos);
        const float4* ap = (const float4*)(eas + (size_t)pos * ED);
        float4 q0 = __ldg(ap + 0);
        float4 q1 = __ldg(ap + 1);
        float4 q2 = __ldg(ap + 2);
        float4 q3 = __ldg(ap + 3);
        float4 ev = bias4;
        float4 w;
        #define EK(a_, k_) \
            w = *(const float4*)(Ws + (k_) * H + f); \
            ev.x += (a_) * w.x; ev.y += (a_) * w.y; \
            ev.z += (a_) * w.z; ev.w += (a_) * w.w;
        EK(q0.x, 0)  EK(q0.y, 1)  EK(q0.z, 2)  EK(q0.w, 3)
        EK(q1.x, 4)  EK(q1.y, 5)  EK(q1.z, 6)  EK(q1.w, 7)
        EK(q2.x, 8)  EK(q2.y, 9)  EK(q2.z, 10) EK(q2.w, 11)
        EK(q3.x, 12) EK(q3.y, 13) EK(q3.z, 14) EK(q3.w, 15)
        #undef EK
        float4 hv = *(const float4*)(h + (size_t)src * H + f);
        acc.x += fmaxf(hv.x + ev.x, 0.f);
        acc.y += fmaxf(hv.y + ev.y, 0.f);
        acc.z += fmaxf(hv.z + ev.z, 0.f);
        acc.w += fmaxf(hv.w + ev.w, 0.f);
    }
    *(float4*)(t + (size_t)n * H + f) = acc;
}

// ---------------- persistent tiled SGEMM: C[M,128] = op(A[M,K]) @ W[K,128] + bias ----
// BN_IN:  apply y = relu(a*scale[k]+shift[k]) to A elements at load time
// STATS:  accumulate per-column sum / sumsq of (acc+bias) into gsum/gsq
// RELU_OUT: relu on output
template<int K, bool BN_IN, bool RELU_OUT, bool STATS>
__global__ void __launch_bounds__(256) gemm_k(
    const float* __restrict__ A, const float* __restrict__ W,
    const float* __restrict__ bias, float* __restrict__ C, int M,
    const float* __restrict__ bscale, const float* __restrict__ bshift,
    float* __restrict__ gsum, float* __restrict__ gsq)
{
    constexpr int NT = K / 8;
    __shared__ __align__(16) float As[2][8][132];
    __shared__ __align__(16) float Bs[2][8][128];
    __shared__ float s_sum[128];
    __shared__ float s_sq[128];

    const int tid = threadIdx.x;
    const int tx  = tid & 15;        // 16 col-groups of 8
    const int ty  = tid >> 4;        // 16 row-groups of 8

    if (STATS && tid < 128) { s_sum[tid] = 0.f; s_sq[tid] = 0.f; }

    const int aRow = tid >> 1;             // 0..127
    const int aK   = (tid & 1) << 2;       // 0 or 4
    const int wK   = tid >> 5;             // 0..7
    const int wN   = (tid & 31) << 2;      // 0..124

    float bias_c[8];
    #pragma unroll
    for (int j = 0; j < 8; j++) bias_c[j] = __ldg(bias + tx * 8 + j);

    const int numTiles = (M + 127) >> 7;
    for (int tile = blockIdx.x; tile < numTiles; tile += gridDim.x) {
        const int rowBlk = tile << 7;

        float acc[8][8];
        #pragma unroll
        for (int r = 0; r < 8; r++)
            #pragma unroll
            for (int c = 0; c < 8; c++) acc[r][c] = 0.f;

        float4 va, vb;
        // ---- prologue: tile 0 ----
        {
            int grow = rowBlk + aRow;
            if (grow < M) {
                va = *(const float4*)(A + (size_t)grow * K + aK);
                if (BN_IN) {
                    int kb = aK;
                    va.x = fmaxf(va.x * __ldg(bscale + kb + 0) + __ldg(bshift + kb + 0), 0.f);
                    va.y = fmaxf(va.y * __ldg(bscale + kb + 1) + __ldg(bshift + kb + 1), 0.f);
                    va.z = fmaxf(va.z * __ldg(bscale + kb + 2) + __ldg(bshift + kb + 2), 0.f);
                    va.w = fmaxf(va.w * __ldg(bscale + kb + 3) + __ldg(bshift + kb + 3), 0.f);
                }
            } else va = make_float4(0.f, 0.f, 0.f, 0.f);
            vb = *(const float4*)(W + (size_t)wK * 128 + wN);
        }
        As[0][aK + 0][aRow] = va.x;
        As[0][aK + 1][aRow] = va.y;
        As[0][aK + 2][aRow] = va.z;
        As[0][aK + 3][aRow] = va.w;
        *(float4*)&Bs[0][wK][wN] = vb;
        __syncthreads();

        for (int kt = 0; kt < NT; kt++) {
            const int cur = kt & 1;
            if (kt + 1 < NT) {
                int gk = (kt + 1) * 8;
                int grow = rowBlk + aRow;
                if (grow < M) {
                    va = *(const float4*)(A + (size_t)grow * K + gk + aK);
                    if (BN_IN) {
                        int kb = gk + aK;
                        va.x = fmaxf(va.x * __ldg(bscale + kb + 0) + __ldg(bshift + kb + 0), 0.f);
                        va.y = fmaxf(va.y * __ldg(bscale + kb + 1) + __ldg(bshift + kb + 1), 0.f);
                        va.z = fmaxf(va.z * __ldg(bscale + kb + 2) + __ldg(bshift + kb + 2), 0.f);
                        va.w = fmaxf(va.w * __ldg(bscale + kb + 3) + __ldg(bshift + kb + 3), 0.f);
                    }
                } else va = make_float4(0.f, 0.f, 0.f, 0.f);
                vb = *(const float4*)(W + (size_t)(gk + wK) * 128 + wN);
            }
            #pragma unroll
            for (int kk = 0; kk < 8; kk++) {
                float4 a0 = *(const float4*)&As[cur][kk][ty * 8];
                float4 a1 = *(const float4*)&As[cur][kk][ty * 8 + 4];
                float4 b0 = *(const float4*)&Bs[cur][kk][tx * 8];
                float4 b1 = *(const float4*)&Bs[cur][kk][tx * 8 + 4];
                float a[8] = {a0.x, a0.y, a0.z, a0.w, a1.x, a1.y, a1.z, a1.w};
                float b[8] = {b0.x, b0.y, b0.z, b0.w, b1.x, b1.y, b1.z, b1.w};
                #pragma unroll
                for (int r = 0; r < 8; r++)
                    #pragma unroll
                    for (int c = 0; c < 8; c++)
                        acc[r][c] += a[r] * b[c];
            }
            if (kt + 1 < NT) {
                const int nxt = cur ^ 1;
                As[nxt][aK + 0][aRow] = va.x;
                As[nxt][aK + 1][aRow] = va.y;
                As[nxt][aK + 2][aRow] = va.z;
                As[nxt][aK + 3][aRow] = va.w;
                *(float4*)&Bs[nxt][wK][wN] = vb;
            }
            __syncthreads();
        }

        // ---- epilogue (registers + global only; safe to overlap with next prologue) ----
        float ps[8], pq[8];
        if (STATS) {
            #pragma unroll
            for (int j = 0; j < 8; j++) { ps[j] = 0.f; pq[j] = 0.f; }
        }

        #pragma unroll
        for (int r = 0; r < 8; r++) {
            int grow = rowBlk + ty * 8 + r;
            if (grow < M) {
                float o[8];
                #pragma unroll
                for (int j = 0; j < 8; j++) {
                    float v = acc[r][j] + bias_c[j];
                    if (STATS) { ps[j] += v; pq[j] += v * v; }
                    if (RELU_OUT) v = fmaxf(v, 0.f);
                    o[j] = v;
                }
                *(float4*)(C + (size_t)grow * 128 + tx * 8)     = make_float4(o[0], o[1], o[2], o[3]);
                *(float4*)(C + (size_t)grow * 128 + tx * 8 + 4) = make_float4(o[4], o[5], o[6], o[7]);
            }
        }

        if (STATS) {
            #pragma unroll
            for (int j = 0; j < 8; j++) {
                atomicAdd(&s_sum[tx * 8 + j], ps[j]);
                atomicAdd(&s_sq [tx * 8 + j], pq[j]);
            }
        }
    }

    if (STATS) {
        __syncthreads();
        if (tid < 128) {
            atomicAdd(gsum + tid, s_sum[tid]);
            atomicAdd(gsq  + tid, s_sq[tid]);
        }
    }
}

// ---------------- BN finalize: scale/shift per column ----------------
__global__ void bn_finalize_kernel(const float* __restrict__ cs, const float* __restrict__ cq,
                                   const float* __restrict__ g, const float* __restrict__ b,
                                   int N, float* __restrict__ scale, float* __restrict__ shift)
{
    int j = threadIdx.x;
    float invN = 1.f / (float)N;
    float mean = cs[j] * invN;
    float var  = cq[j] * invN - mean * mean;
    float inv  = rsqrtf(var + BN_EPS);
    float sc   = g[j] * inv;
    scale[j] = sc;
    shift[j] = b[j] - mean * sc;
}

// ---------------- global add pool (batch is sorted -> run-length local reduce) ----
__global__ void __launch_bounds__(256) pool_kernel(
    const float* __restrict__ h, const int* __restrict__ batch,
    float* __restrict__ pooled, int N)
{
    const int lane = threadIdx.x & 31;
    const int warp = (blockIdx.x * blockDim.x + threadIdx.x) >> 5;
    const int CHUNK = 64;
    int n0 = warp * CHUNK;
    if (n0 >= N) return;
    int n1 = n0 + CHUNK; if (n1 > N) n1 = N;
    const int f = lane * 4;

    int cur = __ldg(batch + n0);
    float4 acc = make_float4(0.f, 0.f, 0.f, 0.f);
    for (int n = n0; n < n1; n++) {
        int b = __ldg(batch + n);
        if (b != cur) {
            red_add_v4(pooled + (size_t)cur * H + f, acc);
            acc = make_float4(0.f, 0.f, 0.f, 0.f);
            cur = b;
        }
        float4 v = *(const float4*)(h + (size_t)n * H + f);
        acc.x += v.x; acc.y += v.y; acc.z += v.z; acc.w += v.w;
    }
    red_add_v4(pooled + (size_t)cur * H + f, acc);
}

// ---------------- final FC: out[G,10] = pooled @ fc_w + fc_b ----------------
__global__ void final_gemm_kernel(const float* __restrict__ pooled,
                                  const float* __restrict__ fcw, const float* __restrict__ fcb,
                                  float* __restrict__ out, int G)
{
    __shared__ float row[H];
    int g = blockIdx.x;
    row[threadIdx.x] = pooled[(size_t)g * H + threadIdx.x];
    __syncthreads();
    if (threadIdx.x < 10) {
        float acc = fcb[threadIdx.x];
        #pragma unroll 8
        for (int k = 0; k < H; k++)
            acc += row[k] * fcw[k * 10 + threadIdx.x];
        out[g * 10 + threadIdx.x] = acc;
    }
}

// ---------------- launch ----------------
extern "C" void kernel_launch(void* const* d_in, const int* in_sizes, int n_in,
                              void* d_out, int out_size)
{
    const float* x      = (const float*)d_in[0];
    const float* ea     = (const float*)d_in[1];
    const float* node_w = (const float*)d_in[2];
    const float* node_b = (const float*)d_in[3];
    const float* edge_w = (const float*)d_in[4];
    const float* edge_b = (const float*)d_in[5];
    const float* lin1_w = (const float*)d_in[6];
    const float* lin1_b = (const float*)d_in[7];
    const float* bn_g   = (const float*)d_in[8];
    const float* bn_b   = (const float*)d_in[9];
    const float* lin2_w = (const float*)d_in[10];
    const float* lin2_b = (const float*)d_in[11];
    const float* fc_w   = (const float*)d_in[12];
    const float* fc_b   = (const float*)d_in[13];
    const int* ei       = (const int*)d_in[14];
    const int* batch    = (const int*)d_in[15];

    const int N = in_sizes[0] / XD;
    const int E = in_sizes[1] / ED;
    const int G = out_size / 10;

    float *hP, *tP, *h1P, *plP, *csP, *cqP, *scP, *shP, *easP;
    int *ssrcP, *cntP, *rowP, *ofsP;
    cudaGetSymbolAddress((void**)&hP,   g_h);
    cudaGetSymbolAddress((void**)&tP,   g_t);
    cudaGetSymbolAddress((void**)&h1P,  g_h1);
    cudaGetSymbolAddress((void**)&plP,  g_pooled);
    cudaGetSymbolAddress((void**)&csP,  g_colsum);
    cudaGetSymbolAddress((void**)&cqP,  g_colsumsq);
    cudaGetSymbolAddress((void**)&scP,  g_scale);
    cudaGetSymbolAddress((void**)&shP,  g_shift);
    cudaGetSymbolAddress((void**)&easP, g_eas);
    cudaGetSymbolAddress((void**)&ssrcP,g_ssrc);
    cudaGetSymbolAddress((void**)&cntP, g_cnt);
    cudaGetSymbolAddress((void**)&rowP, g_row);
    cudaGetSymbolAddress((void**)&ofsP, g_ofs);

    const int GEMM_GRID = 296;  // 2 CTAs/SM x 148 SMs, persistent tile loop

    // ---- CSR build (once per launch; reused by all 3 layers) ----
    cudaMemsetAsync(cntP, 0, N * sizeof(int));
    hist_kernel<<<(E + 255) / 256, 256>>>(ei, cntP, E);
    prefix_kernel<<<1, 1024>>>(cntP, rowP, ofsP, N, E);
    scatter_kernel<<<(E + 255) / 256, 256>>>(ei, ea, ofsP, ssrcP, easP, E);

    // node encoder: h = x @ node_w + node_b
    gemm_k<XD, false, false, false><<<GEMM_GRID, 256>>>(
        x, node_w, node_b, hP, N, nullptr, nullptr, nullptr, nullptr);

    for (int l = 0; l < 3; l++) {
        // t = h + segment_sum(relu(h[src] + e)); also zeroes BN stat accumulators
        aggr_kernel<<<(N * 32 + 255) / 256, 256>>>(
            hP, tP, easP, ssrcP, edge_w, edge_b, rowP, N, csP, cqP);
        // h1 = t @ W1 + b1, with column sum/sumsq accumulation
        gemm_k<H, false, false, true><<<GEMM_GRID, 256>>>(
            tP, lin1_w + (size_t)l * H * H, lin1_b + l * H, h1P, N,
            nullptr, nullptr, csP, cqP);
        // BN scale/shift
        bn_finalize_kernel<<<1, H>>>(csP, cqP, bn_g + l * H, bn_b + l * H, N, scP, shP);
        // h = relu( relu(bn(h1)) @ W2 + b2 )
        gemm_k<H, true, true, false><<<GEMM_GRID, 256>>>(
            h1P, lin2_w + (size_t)l * H * H, lin2_b + l * H, hP, N,
            scP, shP, nullptr, nullptr);
    }

    // pooled = segment_sum(h, batch)
    cudaMemsetAsync(plP, 0, (size_t)G * H * sizeof(float));
    int poolWarps = (N + 63) / 64;
    pool_kernel<<<(poolWarps + 7) / 8, 256>>>(hP, batch, plP, N);

    // out = pooled @ fc_w + fc_b
    final_gemm_kernel<<<G, H>>>(plP, fc_w, fc_b, (float*)d_out, G);
}

// round 8
// speedup vs baseline: 1.0512x; 1.0512x over previous
#include <cuda_runtime.h>
#include <cstdint>

#define H   128
#define XD  64
#define ED  16
#define NMAX 50000
#define EMAX 640000
#define GPMAX 512
#define BN_EPS 1e-5f

// ---------------- scratch (static device globals; no allocation) ----------------
__device__ __align__(16) float g_h  [(size_t)NMAX * H];
__device__ __align__(16) float g_t  [(size_t)NMAX * H];
__device__ __align__(16) float g_h1 [(size_t)NMAX * H];
__device__ __align__(16) float g_pooled[GPMAX * H];
__device__ __align__(16) float g_colsum[H];
__device__ __align__(16) float g_colsumsq[H];
__device__ __align__(16) float g_scale[H];
__device__ __align__(16) float g_shift[H];
// CSR sort scratch
__device__ __align__(16) float g_eas [(size_t)EMAX * ED];  // edge_attr permuted to dst-sorted order
__device__ int   g_ssrc[EMAX];
__device__ int   g_cnt [NMAX];
__device__ int   g_row [NMAX + 1];
__device__ int   g_ofs [NMAX];

// ---------------- helpers ----------------
__device__ __forceinline__ void red_add_v4(float* addr, float4 v) {
    asm volatile("red.global.add.v4.f32 [%0], {%1,%2,%3,%4};"
                 :: "l"(addr), "f"(v.x), "f"(v.y), "f"(v.z), "f"(v.w)
                 : "memory");
}

// ---------------- CSR build: histogram -> scan -> scatter ----------------
__global__ void hist_kernel(const int* __restrict__ ei, int* __restrict__ cnt, int E)
{
    int e = blockIdx.x * blockDim.x + threadIdx.x;
    if (e < E) atomicAdd(&cnt[__ldg(ei + E + e)], 1);
}

__global__ void prefix_kernel(const int* __restrict__ cnt, int* __restrict__ row_ptr,
                              int* __restrict__ ofs, int N, int E)
{
    __shared__ int ssum[1024];
    int tid = threadIdx.x;
    int per = (N + 1023) >> 10;
    int start = tid * per;
    int end = min(start + per, N);
    int s = 0;
    for (int i = start; i < end; i++) s += cnt[i];
    ssum[tid] = s;
    __syncthreads();
    #pragma unroll
    for (int off = 1; off < 1024; off <<= 1) {
        int v = (tid >= off) ? ssum[tid - off] : 0;
        __syncthreads();
        ssum[tid] += v;
        __syncthreads();
    }
    int run = (tid > 0) ? ssum[tid - 1] : 0;
    for (int i = start; i < end; i++) {
        row_ptr[i] = run;
        ofs[i] = run;
        run += cnt[i];
    }
    if (tid == 0) row_ptr[N] = E;
}

__global__ void scatter_kernel(const int* __restrict__ ei, const float* __restrict__ ea,
                               int* __restrict__ ofs, int* __restrict__ ssrc,
                               float* __restrict__ eas, int E)
{
    int e = blockIdx.x * blockDim.x + threadIdx.x;
    if (e >= E) return;
    int dst = __ldg(ei + E + e);
    int pos = atomicAdd(&ofs[dst], 1);
    ssrc[pos] = __ldg(ei + e);
    const float4* s = (const float4*)(ea + (size_t)e * ED);
    float4* d = (float4*)(eas + (size_t)pos * ED);
    d[0] = __ldg(s + 0);
    d[1] = __ldg(s + 1);
    d[2] = __ldg(s + 2);
    d[3] = __ldg(s + 3);
}

// ------- aggregation: t[n] = h[n] + sum_{e: dst=n} relu(h[src_e] + ea_e @ Ew + Eb) ------
__global__ void __launch_bounds__(256) aggr_kernel(
    const float* __restrict__ h, float* __restrict__ t,
    const float* __restrict__ eas, const int* __restrict__ ssrc,
    const float* __restrict__ eW, const float* __restrict__ eb,
    const int* __restrict__ row_ptr, int N,
    float* __restrict__ cs, float* __restrict__ cq)
{
    __shared__ __align__(16) float Ws[ED * H];
    __shared__ __align__(16) float ebs[H];
    for (int i = threadIdx.x; i < ED * H; i += blockDim.x) Ws[i] = eW[i];
    if (threadIdx.x < H) ebs[threadIdx.x] = eb[threadIdx.x];
    __syncthreads();
    if (blockIdx.x == 0 && threadIdx.x < H) { cs[threadIdx.x] = 0.f; cq[threadIdx.x] = 0.f; }

    const int lane = threadIdx.x & 31;
    const int f = lane * 4;
    int n = (blockIdx.x * blockDim.x + threadIdx.x) >> 5;
    if (n >= N) return;

    int beg = __ldg(row_ptr + n);
    int end = __ldg(row_ptr + n + 1);
    float4 acc = *(const float4*)(h + (size_t)n * H + f);   // self term (eps=0)
    const float4 bias4 = *(const float4*)(ebs + f);

    for (int pos = beg; pos < end; pos++) {
        int src = __ldg(ssrc + pos);
        const float4* ap = (const float4*)(eas + (size_t)pos * ED);
        float4 q0 = __ldg(ap + 0);
        float4 q1 = __ldg(ap + 1);
        float4 q2 = __ldg(ap + 2);
        float4 q3 = __ldg(ap + 3);
        float4 ev = bias4;
        float4 w;
        #define EK(a_, k_) \
            w = *(const float4*)(Ws + (k_) * H + f); \
            ev.x += (a_) * w.x; ev.y += (a_) * w.y; \
            ev.z += (a_) * w.z; ev.w += (a_) * w.w;
        EK(q0.x, 0)  EK(q0.y, 1)  EK(q0.z, 2)  EK(q0.w, 3)
        EK(q1.x, 4)  EK(q1.y, 5)  EK(q1.z, 6)  EK(q1.w, 7)
        EK(q2.x, 8)  EK(q2.y, 9)  EK(q2.z, 10) EK(q2.w, 11)
        EK(q3.x, 12) EK(q3.y, 13) EK(q3.z, 14) EK(q3.w, 15)
        #undef EK
        float4 hv = *(const float4*)(h + (size_t)src * H + f);
        acc.x += fmaxf(hv.x + ev.x, 0.f);
        acc.y += fmaxf(hv.y + ev.y, 0.f);
        acc.z += fmaxf(hv.z + ev.z, 0.f);
        acc.w += fmaxf(hv.w + ev.w, 0.f);
    }
    *(float4*)(t + (size_t)n * H + f) = acc;
}

// ---------------- tiled SGEMM with packed f32x2 FMA ----------------
// C[M,128] = op(A[M,K]) @ W[K,128] + bias
// BN_IN:  y = relu(a*scale[k]+shift[k]) applied to A at load
// STATS:  per-column sum/sumsq of (acc+bias) accumulated to gsum/gsq
// RELU_OUT: relu on output
#define FMA2(acc_, a_, b_) \
    asm("fma.rn.f32x2 %0, %1, %2, %0;" : "+l"(acc_) : "l"(a_), "l"(b_))

template<int K, bool BN_IN, bool RELU_OUT, bool STATS>
__global__ void __launch_bounds__(256, 2) gemm_k(
    const float* __restrict__ A, const float* __restrict__ W,
    const float* __restrict__ bias, float* __restrict__ C, int M,
    const float* __restrict__ bscale, const float* __restrict__ bshift,
    float* __restrict__ gsum, float* __restrict__ gsq)
{
    constexpr int NT = K / 8;
    __shared__ __align__(16) float As[2][8][132];
    __shared__ __align__(16) float Bs[2][8][128];
    __shared__ float s_sum[128];
    __shared__ float s_sq[128];

    const int tid = threadIdx.x;
    const int tx  = tid & 15;        // 16 col-groups of 8
    const int ty  = tid >> 4;        // 16 row-groups of 8
    const int rowBlk = blockIdx.x * 128;

    if (STATS && tid < 128) { s_sum[tid] = 0.f; s_sq[tid] = 0.f; }

    const int aRow = tid >> 1;             // 0..127
    const int aK   = (tid & 1) << 2;       // 0 or 4
    const int wK   = tid >> 5;             // 0..7
    const int wN   = (tid & 31) << 2;      // 0..124

    // packed accumulators: accP[r][c] holds cols (2c, 2c+1) for row r
    unsigned long long accP[8][4];
    #pragma unroll
    for (int r = 0; r < 8; r++)
        #pragma unroll
        for (int c = 0; c < 4; c++) accP[r][c] = 0ull;

    float4 va, vb;
    // ---- prologue: k-tile 0 ----
    {
        int grow = rowBlk + aRow;
        if (grow < M) {
            va = *(const float4*)(A + (size_t)grow * K + aK);
            if (BN_IN) {
                int kb = aK;
                va.x = fmaxf(va.x * __ldg(bscale + kb + 0) + __ldg(bshift + kb + 0), 0.f);
                va.y = fmaxf(va.y * __ldg(bscale + kb + 1) + __ldg(bshift + kb + 1), 0.f);
                va.z = fmaxf(va.z * __ldg(bscale + kb + 2) + __ldg(bshift + kb + 2), 0.f);
                va.w = fmaxf(va.w * __ldg(bscale + kb + 3) + __ldg(bshift + kb + 3), 0.f);
            }
        } else va = make_float4(0.f, 0.f, 0.f, 0.f);
        vb = *(const float4*)(W + (size_t)wK * 128 + wN);
    }
    As[0][aK + 0][aRow] = va.x;
    As[0][aK + 1][aRow] = va.y;
    As[0][aK + 2][aRow] = va.z;
    As[0][aK + 3][aRow] = va.w;
    *(float4*)&Bs[0][wK][wN] = vb;
    __syncthreads();

    for (int kt = 0; kt < NT; kt++) {
        const int cur = kt & 1;
        if (kt + 1 < NT) {
            int gk = (kt + 1) * 8;
            int grow = rowBlk + aRow;
            if (grow < M) {
                va = *(const float4*)(A + (size_t)grow * K + gk + aK);
                if (BN_IN) {
                    int kb = gk + aK;
                    va.x = fmaxf(va.x * __ldg(bscale + kb + 0) + __ldg(bshift + kb + 0), 0.f);
                    va.y = fmaxf(va.y * __ldg(bscale + kb + 1) + __ldg(bshift + kb + 1), 0.f);
                    va.z = fmaxf(va.z * __ldg(bscale + kb + 2) + __ldg(bshift + kb + 2), 0.f);
                    va.w = fmaxf(va.w * __ldg(bscale + kb + 3) + __ldg(bshift + kb + 3), 0.f);
                }
            } else va = make_float4(0.f, 0.f, 0.f, 0.f);
            vb = *(const float4*)(W + (size_t)(gk + wK) * 128 + wN);
        }
        #pragma unroll
        for (int kk = 0; kk < 8; kk++) {
            float4 a0 = *(const float4*)&As[cur][kk][ty * 8];
            float4 a1 = *(const float4*)&As[cur][kk][ty * 8 + 4];
            // B pairs are adjacent floats: load as already-packed 64-bit lanes
            ulonglong2 bq0 = *(const ulonglong2*)&Bs[cur][kk][tx * 8];
            ulonglong2 bq1 = *(const ulonglong2*)&Bs[cur][kk][tx * 8 + 4];
            unsigned long long bP0 = bq0.x, bP1 = bq0.y, bP2 = bq1.x, bP3 = bq1.y;
            float a[8] = {a0.x, a0.y, a0.z, a0.w, a1.x, a1.y, a1.z, a1.w};
            #pragma unroll
            for (int r = 0; r < 8; r++) {
                unsigned long long aP;
                asm("mov.b64 %0, {%1, %1};" : "=l"(aP) : "f"(a[r]));
                FMA2(accP[r][0], aP, bP0);
                FMA2(accP[r][1], aP, bP1);
                FMA2(accP[r][2], aP, bP2);
                FMA2(accP[r][3], aP, bP3);
            }
        }
        if (kt + 1 < NT) {
            const int nxt = cur ^ 1;
            As[nxt][aK + 0][aRow] = va.x;
            As[nxt][aK + 1][aRow] = va.y;
            As[nxt][aK + 2][aRow] = va.z;
            As[nxt][aK + 3][aRow] = va.w;
            *(float4*)&Bs[nxt][wK][wN] = vb;
        }
        __syncthreads();
    }

    // ---- epilogue ----
    float bias_c[8];
    #pragma unroll
    for (int j = 0; j < 8; j++) bias_c[j] = __ldg(bias + tx * 8 + j);

    float ps[8], pq[8];
    if (STATS) {
        #pragma unroll
        for (int j = 0; j < 8; j++) { ps[j] = 0.f; pq[j] = 0.f; }
    }

    #pragma unroll
    for (int r = 0; r < 8; r++) {
        int grow = rowBlk + ty * 8 + r;
        if (grow < M) {
            float o[8];
            #pragma unroll
            for (int c = 0; c < 4; c++) {
                float lo, hi;
                asm("mov.b64 {%0, %1}, %2;" : "=f"(lo), "=f"(hi) : "l"(accP[r][c]));
                o[2 * c]     = lo;
                o[2 * c + 1] = hi;
            }
            #pragma unroll
            for (int j = 0; j < 8; j++) {
                float v = o[j] + bias_c[j];
                if (STATS) { ps[j] += v; pq[j] += v * v; }
                if (RELU_OUT) v = fmaxf(v, 0.f);
                o[j] = v;
            }
            *(float4*)(C + (size_t)grow * 128 + tx * 8)     = make_float4(o[0], o[1], o[2], o[3]);
            *(float4*)(C + (size_t)grow * 128 + tx * 8 + 4) = make_float4(o[4], o[5], o[6], o[7]);
        }
    }

    if (STATS) {
        #pragma unroll
        for (int j = 0; j < 8; j++) {
            atomicAdd(&s_sum[tx * 8 + j], ps[j]);
            atomicAdd(&s_sq [tx * 8 + j], pq[j]);
        }
        __syncthreads();
        if (tid < 128) {
            atomicAdd(gsum + tid, s_sum[tid]);
            atomicAdd(gsq  + tid, s_sq[tid]);
        }
    }
}

// ---------------- BN finalize: scale/shift per column ----------------
__global__ void bn_finalize_kernel(const float* __restrict__ cs, const float* __restrict__ cq,
                                   const float* __restrict__ g, const float* __restrict__ b,
                                   int N, float* __restrict__ scale, float* __restrict__ shift)
{
    int j = threadIdx.x;
    float invN = 1.f / (float)N;
    float mean = cs[j] * invN;
    float var  = cq[j] * invN - mean * mean;
    float inv  = rsqrtf(var + BN_EPS);
    float sc   = g[j] * inv;
    scale[j] = sc;
    shift[j] = b[j] - mean * sc;
}

// ---------------- global add pool (batch is sorted -> run-length local reduce) ----
__global__ void __launch_bounds__(256) pool_kernel(
    const float* __restrict__ h, const int* __restrict__ batch,
    float* __restrict__ pooled, int N)
{
    const int lane = threadIdx.x & 31;
    const int warp = (blockIdx.x * blockDim.x + threadIdx.x) >> 5;
    const int CHUNK = 64;
    int n0 = warp * CHUNK;
    if (n0 >= N) return;
    int n1 = n0 + CHUNK; if (n1 > N) n1 = N;
    const int f = lane * 4;

    int cur = __ldg(batch + n0);
    float4 acc = make_float4(0.f, 0.f, 0.f, 0.f);
    for (int n = n0; n < n1; n++) {
        int b = __ldg(batch + n);
        if (b != cur) {
            red_add_v4(pooled + (size_t)cur * H + f, acc);
            acc = make_float4(0.f, 0.f, 0.f, 0.f);
            cur = b;
        }
        float4 v = *(const float4*)(h + (size_t)n * H + f);
        acc.x += v.x; acc.y += v.y; acc.z += v.z; acc.w += v.w;
    }
    red_add_v4(pooled + (size_t)cur * H + f, acc);
}

// ---------------- final FC: out[G,10] = pooled @ fc_w + fc_b ----------------
__global__ void final_gemm_kernel(const float* __restrict__ pooled,
                                  const float* __restrict__ fcw, const float* __restrict__ fcb,
                                  float* __restrict__ out, int G)
{
    __shared__ float row[H];
    int g = blockIdx.x;
    row[threadIdx.x] = pooled[(size_t)g * H + threadIdx.x];
    __syncthreads();
    if (threadIdx.x < 10) {
        float acc = fcb[threadIdx.x];
        #pragma unroll 8
        for (int k = 0; k < H; k++)
            acc += row[k] * fcw[k * 10 + threadIdx.x];
        out[g * 10 + threadIdx.x] = acc;
    }
}

// ---------------- launch ----------------
extern "C" void kernel_launch(void* const* d_in, const int* in_sizes, int n_in,
                              void* d_out, int out_size)
{
    const float* x      = (const float*)d_in[0];
    const float* ea     = (const float*)d_in[1];
    const float* node_w = (const float*)d_in[2];
    const float* node_b = (const float*)d_in[3];
    const float* edge_w = (const float*)d_in[4];
    const float* edge_b = (const float*)d_in[5];
    const float* lin1_w = (const float*)d_in[6];
    const float* lin1_b = (const float*)d_in[7];
    const float* bn_g   = (const float*)d_in[8];
    const float* bn_b   = (const float*)d_in[9];
    const float* lin2_w = (const float*)d_in[10];
    const float* lin2_b = (const float*)d_in[11];
    const float* fc_w   = (const float*)d_in[12];
    const float* fc_b   = (const float*)d_in[13];
    const int* ei       = (const int*)d_in[14];
    const int* batch    = (const int*)d_in[15];

    const int N = in_sizes[0] / XD;
    const int E = in_sizes[1] / ED;
    const int G = out_size / 10;

    float *hP, *tP, *h1P, *plP, *csP, *cqP, *scP, *shP, *easP;
    int *ssrcP, *cntP, *rowP, *ofsP;
    cudaGetSymbolAddress((void**)&hP,   g_h);
    cudaGetSymbolAddress((void**)&tP,   g_t);
    cudaGetSymbolAddress((void**)&h1P,  g_h1);
    cudaGetSymbolAddress((void**)&plP,  g_pooled);
    cudaGetSymbolAddress((void**)&csP,  g_colsum);
    cudaGetSymbolAddress((void**)&cqP,  g_colsumsq);
    cudaGetSymbolAddress((void**)&scP,  g_scale);
    cudaGetSymbolAddress((void**)&shP,  g_shift);
    cudaGetSymbolAddress((void**)&easP, g_eas);
    cudaGetSymbolAddress((void**)&ssrcP,g_ssrc);
    cudaGetSymbolAddress((void**)&cntP, g_cnt);
    cudaGetSymbolAddress((void**)&rowP, g_row);
    cudaGetSymbolAddress((void**)&ofsP, g_ofs);

    const int gemmGrid = (N + 127) / 128;

    // ---- CSR build (once per launch; reused by all 3 layers) ----
    cudaMemsetAsync(cntP, 0, N * sizeof(int));
    hist_kernel<<<(E + 255) / 256, 256>>>(ei, cntP, E);
    prefix_kernel<<<1, 1024>>>(cntP, rowP, ofsP, N, E);
    scatter_kernel<<<(E + 255) / 256, 256>>>(ei, ea, ofsP, ssrcP, easP, E);

    // node encoder: h = x @ node_w + node_b
    gemm_k<XD, false, false, false><<<gemmGrid, 256>>>(
        x, node_w, node_b, hP, N, nullptr, nullptr, nullptr, nullptr);

    for (int l = 0; l < 3; l++) {
        // t = h + segment_sum(relu(h[src] + e)); also zeroes BN stat accumulators
        aggr_kernel<<<(N * 32 + 255) / 256, 256>>>(
            hP, tP, easP, ssrcP, edge_w, edge_b, rowP, N, csP, cqP);
        // h1 = t @ W1 + b1, with column sum/sumsq accumulation
        gemm_k<H, false, false, true><<<gemmGrid, 256>>>(
            tP, lin1_w + (size_t)l * H * H, lin1_b + l * H, h1P, N,
            nullptr, nullptr, csP, cqP);
        // BN scale/shift
        bn_finalize_kernel<<<1, H>>>(csP, cqP, bn_g + l * H, bn_b + l * H, N, scP, shP);
        // h = relu( relu(bn(h1)) @ W2 + b2 )
        gemm_k<H, true, true, false><<<gemmGrid, 256>>>(
            h1P, lin2_w + (size_t)l * H * H, lin2_b + l * H, hP, N,
            scP, shP, nullptr, nullptr);
    }

    // pooled = segment_sum(h, batch)
    cudaMemsetAsync(plP, 0, (size_t)G * H * sizeof(float));
    int poolWarps = (N + 63) / 64;
    pool_kernel<<<(poolWarps + 7) / 8, 256>>>(hP, batch, plP, N);

    // out = pooled @ fc_w + fc_b
    final_gemm_kernel<<<G, H>>>(plP, fc_w, fc_b, (float*)d_out, G);
}

// round 9
// speedup vs baseline: 1.2271x; 1.1673x over previous
#include <cuda_runtime.h>
#include <cstdint>

#define H   128
#define XD  64
#define ED  16
#define NMAX 50000
#define EMAX 640000
#define GPMAX 512
#define BN_EPS 1e-5f

// ---------------- scratch (static device globals; no allocation) ----------------
__device__ __align__(16) float g_h  [(size_t)NMAX * H];
__device__ __align__(16) float g_t  [(size_t)NMAX * H];
__device__ __align__(16) float g_h1 [(size_t)NMAX * H];
__device__ __align__(16) float g_pooled[GPMAX * H];
__device__ __align__(16) float g_colsum[H];
__device__ __align__(16) float g_colsumsq[H];
__device__ __align__(16) float g_scale[H];
__device__ __align__(16) float g_shift[H];
// edge features precomputed ONCE (layer-invariant), stored dst-sorted
__device__ __align__(16) float g_esort[(size_t)EMAX * H];   // 327 MB
__device__ int   g_ssrc [EMAX];
__device__ int   g_eperm[EMAX];
__device__ int   g_cnt  [NMAX];
__device__ int   g_row  [NMAX + 1];
__device__ int   g_ofs  [NMAX];

// ---------------- helpers ----------------
__device__ __forceinline__ void red_add_v4(float* addr, float4 v) {
    asm volatile("red.global.add.v4.f32 [%0], {%1,%2,%3,%4};"
                 :: "l"(addr), "f"(v.x), "f"(v.y), "f"(v.z), "f"(v.w)
                 : "memory");
}

// ---------------- CSR build: histogram -> scan -> scatter ----------------
__global__ void hist_kernel(const int* __restrict__ ei, int* __restrict__ cnt, int E)
{
    int e = blockIdx.x * blockDim.x + threadIdx.x;
    if (e < E) atomicAdd(&cnt[__ldg(ei + E + e)], 1);
}

__global__ void prefix_kernel(const int* __restrict__ cnt, int* __restrict__ row_ptr,
                              int* __restrict__ ofs, int N, int E)
{
    __shared__ int ssum[1024];
    int tid = threadIdx.x;
    int per = (N + 1023) >> 10;
    int start = tid * per;
    int end = min(start + per, N);
    int s = 0;
    for (int i = start; i < end; i++) s += cnt[i];
    ssum[tid] = s;
    __syncthreads();
    #pragma unroll
    for (int off = 1; off < 1024; off <<= 1) {
        int v = (tid >= off) ? ssum[tid - off] : 0;
        __syncthreads();
        ssum[tid] += v;
        __syncthreads();
    }
    int run = (tid > 0) ? ssum[tid - 1] : 0;
    for (int i = start; i < end; i++) {
        row_ptr[i] = run;
        ofs[i] = run;
        run += cnt[i];
    }
    if (tid == 0) row_ptr[N] = E;
}

__global__ void scatter_kernel(const int* __restrict__ ei,
                               int* __restrict__ ofs, int* __restrict__ ssrc,
                               int* __restrict__ eperm, int E)
{
    int e = blockIdx.x * blockDim.x + threadIdx.x;
    if (e >= E) return;
    int dst = __ldg(ei + E + e);
    int pos = atomicAdd(&ofs[dst], 1);
    ssrc[pos] = __ldg(ei + e);
    eperm[pos] = e;
}

// ---------------- edge MLP precompute (ONCE): esort[pos] = ea[eperm[pos]] @ Ew + Eb ----
// one warp per sorted position; lane owns 4 features
__global__ void __launch_bounds__(256) ecomp_kernel(
    const float* __restrict__ ea, const int* __restrict__ eperm,
    const float* __restrict__ eW, const float* __restrict__ eb,
    float* __restrict__ esort, int E)
{
    __shared__ __align__(16) float Ws[ED * H];
    __shared__ __align__(16) float ebs[H];
    for (int i = threadIdx.x; i < ED * H; i += blockDim.x) Ws[i] = eW[i];
    if (threadIdx.x < H) ebs[threadIdx.x] = eb[threadIdx.x];
    __syncthreads();

    const int lane = threadIdx.x & 31;
    const int f = lane * 4;
    int pos = (blockIdx.x * blockDim.x + threadIdx.x) >> 5;
    if (pos >= E) return;

    int e = __ldg(eperm + pos);
    const float4* ap = (const float4*)(ea + (size_t)e * ED);
    float4 q0 = __ldg(ap + 0);
    float4 q1 = __ldg(ap + 1);
    float4 q2 = __ldg(ap + 2);
    float4 q3 = __ldg(ap + 3);
    float4 ev = *(const float4*)(ebs + f);
    float4 w;
    #define EK(a_, k_) \
        w = *(const float4*)(Ws + (k_) * H + f); \
        ev.x += (a_) * w.x; ev.y += (a_) * w.y; \
        ev.z += (a_) * w.z; ev.w += (a_) * w.w;
    EK(q0.x, 0)  EK(q0.y, 1)  EK(q0.z, 2)  EK(q0.w, 3)
    EK(q1.x, 4)  EK(q1.y, 5)  EK(q1.z, 6)  EK(q1.w, 7)
    EK(q2.x, 8)  EK(q2.y, 9)  EK(q2.z, 10) EK(q2.w, 11)
    EK(q3.x, 12) EK(q3.y, 13) EK(q3.z, 14) EK(q3.w, 15)
    #undef EK
    *(float4*)(esort + (size_t)pos * H + f) = ev;
}

// ------- aggregation (per layer): t[n] = h[n] + sum_{pos in row n} relu(h[ssrc[pos]] + esort[pos]) ------
// one warp per node; pure memory + 12 fp ops per edge per lane
__global__ void __launch_bounds__(256) aggr_kernel(
    const float* __restrict__ h, float* __restrict__ t,
    const float* __restrict__ esort, const int* __restrict__ ssrc,
    const int* __restrict__ row_ptr, int N,
    float* __restrict__ cs, float* __restrict__ cq)
{
    if (blockIdx.x == 0 && threadIdx.x < H) { cs[threadIdx.x] = 0.f; cq[threadIdx.x] = 0.f; }

    const int lane = threadIdx.x & 31;
    const int f = lane * 4;
    int n = (blockIdx.x * blockDim.x + threadIdx.x) >> 5;
    if (n >= N) return;

    int beg = __ldg(row_ptr + n);
    int end = __ldg(row_ptr + n + 1);
    float4 acc = *(const float4*)(h + (size_t)n * H + f);   // self term (eps=0)

    int pos = beg;
    // unroll-by-2 for memory-level parallelism
    for (; pos + 2 <= end; pos += 2) {
        int s0 = __ldg(ssrc + pos);
        int s1 = __ldg(ssrc + pos + 1);
        float4 e0 = *(const float4*)(esort + (size_t)pos * H + f);
        float4 e1 = *(const float4*)(esort + (size_t)(pos + 1) * H + f);
        float4 h0 = *(const float4*)(h + (size_t)s0 * H + f);
        float4 h1 = *(const float4*)(h + (size_t)s1 * H + f);
        acc.x += fmaxf(h0.x + e0.x, 0.f) + fmaxf(h1.x + e1.x, 0.f);
        acc.y += fmaxf(h0.y + e0.y, 0.f) + fmaxf(h1.y + e1.y, 0.f);
        acc.z += fmaxf(h0.z + e0.z, 0.f) + fmaxf(h1.z + e1.z, 0.f);
        acc.w += fmaxf(h0.w + e0.w, 0.f) + fmaxf(h1.w + e1.w, 0.f);
    }
    if (pos < end) {
        int s0 = __ldg(ssrc + pos);
        float4 e0 = *(const float4*)(esort + (size_t)pos * H + f);
        float4 h0 = *(const float4*)(h + (size_t)s0 * H + f);
        acc.x += fmaxf(h0.x + e0.x, 0.f);
        acc.y += fmaxf(h0.y + e0.y, 0.f);
        acc.z += fmaxf(h0.z + e0.z, 0.f);
        acc.w += fmaxf(h0.w + e0.w, 0.f);
    }
    *(float4*)(t + (size_t)n * H + f) = acc;
}

// ---------------- tiled SGEMM with packed f32x2 FMA ----------------
#define FMA2(acc_, a_, b_) \
    asm("fma.rn.f32x2 %0, %1, %2, %0;" : "+l"(acc_) : "l"(a_), "l"(b_))

template<int K, bool BN_IN, bool RELU_OUT, bool STATS>
__global__ void __launch_bounds__(256, 2) gemm_k(
    const float* __restrict__ A, const float* __restrict__ W,
    const float* __restrict__ bias, float* __restrict__ C, int M,
    const float* __restrict__ bscale, const float* __restrict__ bshift,
    float* __restrict__ gsum, float* __restrict__ gsq)
{
    constexpr int NT = K / 8;
    __shared__ __align__(16) float As[2][8][132];
    __shared__ __align__(16) float Bs[2][8][128];
    __shared__ float s_sum[128];
    __shared__ float s_sq[128];

    const int tid = threadIdx.x;
    const int tx  = tid & 15;
    const int ty  = tid >> 4;
    const int rowBlk = blockIdx.x * 128;

    if (STATS && tid < 128) { s_sum[tid] = 0.f; s_sq[tid] = 0.f; }

    const int aRow = tid >> 1;
    const int aK   = (tid & 1) << 2;
    const int wK   = tid >> 5;
    const int wN   = (tid & 31) << 2;

    unsigned long long accP[8][4];
    #pragma unroll
    for (int r = 0; r < 8; r++)
        #pragma unroll
        for (int c = 0; c < 4; c++) accP[r][c] = 0ull;

    float4 va, vb;
    {
        int grow = rowBlk + aRow;
        if (grow < M) {
            va = *(const float4*)(A + (size_t)grow * K + aK);
            if (BN_IN) {
                int kb = aK;
                va.x = fmaxf(va.x * __ldg(bscale + kb + 0) + __ldg(bshift + kb + 0), 0.f);
                va.y = fmaxf(va.y * __ldg(bscale + kb + 1) + __ldg(bshift + kb + 1), 0.f);
                va.z = fmaxf(va.z * __ldg(bscale + kb + 2) + __ldg(bshift + kb + 2), 0.f);
                va.w = fmaxf(va.w * __ldg(bscale + kb + 3) + __ldg(bshift + kb + 3), 0.f);
            }
        } else va = make_float4(0.f, 0.f, 0.f, 0.f);
        vb = *(const float4*)(W + (size_t)wK * 128 + wN);
    }
    As[0][aK + 0][aRow] = va.x;
    As[0][aK + 1][aRow] = va.y;
    As[0][aK + 2][aRow] = va.z;
    As[0][aK + 3][aRow] = va.w;
    *(float4*)&Bs[0][wK][wN] = vb;
    __syncthreads();

    for (int kt = 0; kt < NT; kt++) {
        const int cur = kt & 1;
        if (kt + 1 < NT) {
            int gk = (kt + 1) * 8;
            int grow = rowBlk + aRow;
            if (grow < M) {
                va = *(const float4*)(A + (size_t)grow * K + gk + aK);
                if (BN_IN) {
                    int kb = gk + aK;
                    va.x = fmaxf(va.x * __ldg(bscale + kb + 0) + __ldg(bshift + kb + 0), 0.f);
                    va.y = fmaxf(va.y * __ldg(bscale + kb + 1) + __ldg(bshift + kb + 1), 0.f);
                    va.z = fmaxf(va.z * __ldg(bscale + kb + 2) + __ldg(bshift + kb + 2), 0.f);
                    va.w = fmaxf(va.w * __ldg(bscale + kb + 3) + __ldg(bshift + kb + 3), 0.f);
                }
            } else va = make_float4(0.f, 0.f, 0.f, 0.f);
            vb = *(const float4*)(W + (size_t)(gk + wK) * 128 + wN);
        }
        #pragma unroll
        for (int kk = 0; kk < 8; kk++) {
            float4 a0 = *(const float4*)&As[cur][kk][ty * 8];
            float4 a1 = *(const float4*)&As[cur][kk][ty * 8 + 4];
            ulonglong2 bq0 = *(const ulonglong2*)&Bs[cur][kk][tx * 8];
            ulonglong2 bq1 = *(const ulonglong2*)&Bs[cur][kk][tx * 8 + 4];
            unsigned long long bP0 = bq0.x, bP1 = bq0.y, bP2 = bq1.x, bP3 = bq1.y;
            float a[8] = {a0.x, a0.y, a0.z, a0.w, a1.x, a1.y, a1.z, a1.w};
            #pragma unroll
            for (int r = 0; r < 8; r++) {
                unsigned long long aP;
                asm("mov.b64 %0, {%1, %1};" : "=l"(aP) : "f"(a[r]));
                FMA2(accP[r][0], aP, bP0);
                FMA2(accP[r][1], aP, bP1);
                FMA2(accP[r][2], aP, bP2);
                FMA2(accP[r][3], aP, bP3);
            }
        }
        if (kt + 1 < NT) {
            const int nxt = cur ^ 1;
            As[nxt][aK + 0][aRow] = va.x;
            As[nxt][aK + 1][aRow] = va.y;
            As[nxt][aK + 2][aRow] = va.z;
            As[nxt][aK + 3][aRow] = va.w;
            *(float4*)&Bs[nxt][wK][wN] = vb;
        }
        __syncthreads();
    }

    float bias_c[8];
    #pragma unroll
    for (int j = 0; j < 8; j++) bias_c[j] = __ldg(bias + tx * 8 + j);

    float ps[8], pq[8];
    if (STATS) {
        #pragma unroll
        for (int j = 0; j < 8; j++) { ps[j] = 0.f; pq[j] = 0.f; }
    }

    #pragma unroll
    for (int r = 0; r < 8; r++) {
        int grow = rowBlk + ty * 8 + r;
        if (grow < M) {
            float o[8];
            #pragma unroll
            for (int c = 0; c < 4; c++) {
                float lo, hi;
                asm("mov.b64 {%0, %1}, %2;" : "=f"(lo), "=f"(hi) : "l"(accP[r][c]));
                o[2 * c]     = lo;
                o[2 * c + 1] = hi;
            }
            #pragma unroll
            for (int j = 0; j < 8; j++) {
                float v = o[j] + bias_c[j];
                if (STATS) { ps[j] += v; pq[j] += v * v; }
                if (RELU_OUT) v = fmaxf(v, 0.f);
                o[j] = v;
            }
            *(float4*)(C + (size_t)grow * 128 + tx * 8)     = make_float4(o[0], o[1], o[2], o[3]);
            *(float4*)(C + (size_t)grow * 128 + tx * 8 + 4) = make_float4(o[4], o[5], o[6], o[7]);
        }
    }

    if (STATS) {
        #pragma unroll
        for (int j = 0; j < 8; j++) {
            atomicAdd(&s_sum[tx * 8 + j], ps[j]);
            atomicAdd(&s_sq [tx * 8 + j], pq[j]);
        }
        __syncthreads();
        if (tid < 128) {
            atomicAdd(gsum + tid, s_sum[tid]);
            atomicAdd(gsq  + tid, s_sq[tid]);
        }
    }
}

// ---------------- BN finalize ----------------
__global__ void bn_finalize_kernel(const float* __restrict__ cs, const float* __restrict__ cq,
                                   const float* __restrict__ g, const float* __restrict__ b,
                                   int N, float* __restrict__ scale, float* __restrict__ shift)
{
    int j = threadIdx.x;
    float invN = 1.f / (float)N;
    float mean = cs[j] * invN;
    float var  = cq[j] * invN - mean * mean;
    float inv  = rsqrtf(var + BN_EPS);
    float sc   = g[j] * inv;
    scale[j] = sc;
    shift[j] = b[j] - mean * sc;
}

// ---------------- global add pool ----------------
__global__ void __launch_bounds__(256) pool_kernel(
    const float* __restrict__ h, const int* __restrict__ batch,
    float* __restrict__ pooled, int N)
{
    const int lane = threadIdx.x & 31;
    const int warp = (blockIdx.x * blockDim.x + threadIdx.x) >> 5;
    const int CHUNK = 64;
    int n0 = warp * CHUNK;
    if (n0 >= N) return;
    int n1 = n0 + CHUNK; if (n1 > N) n1 = N;
    const int f = lane * 4;

    int cur = __ldg(batch + n0);
    float4 acc = make_float4(0.f, 0.f, 0.f, 0.f);
    for (int n = n0; n < n1; n++) {
        int b = __ldg(batch + n);
        if (b != cur) {
            red_add_v4(pooled + (size_t)cur * H + f, acc);
            acc = make_float4(0.f, 0.f, 0.f, 0.f);
            cur = b;
        }
        float4 v = *(const float4*)(h + (size_t)n * H + f);
        acc.x += v.x; acc.y += v.y; acc.z += v.z; acc.w += v.w;
    }
    red_add_v4(pooled + (size_t)cur * H + f, acc);
}

// ---------------- final FC ----------------
__global__ void final_gemm_kernel(const float* __restrict__ pooled,
                                  const float* __restrict__ fcw, const float* __restrict__ fcb,
                                  float* __restrict__ out, int G)
{
    __shared__ float row[H];
    int g = blockIdx.x;
    row[threadIdx.x] = pooled[(size_t)g * H + threadIdx.x];
    __syncthreads();
    if (threadIdx.x < 10) {
        float acc = fcb[threadIdx.x];
        #pragma unroll 8
        for (int k = 0; k < H; k++)
            acc += row[k] * fcw[k * 10 + threadIdx.x];
        out[g * 10 + threadIdx.x] = acc;
    }
}

// ---------------- launch ----------------
extern "C" void kernel_launch(void* const* d_in, const int* in_sizes, int n_in,
                              void* d_out, int out_size)
{
    const float* x      = (const float*)d_in[0];
    const float* ea     = (const float*)d_in[1];
    const float* node_w = (const float*)d_in[2];
    const float* node_b = (const float*)d_in[3];
    const float* edge_w = (const float*)d_in[4];
    const float* edge_b = (const float*)d_in[5];
    const float* lin1_w = (const float*)d_in[6];
    const float* lin1_b = (const float*)d_in[7];
    const float* bn_g   = (const float*)d_in[8];
    const float* bn_b   = (const float*)d_in[9];
    const float* lin2_w = (const float*)d_in[10];
    const float* lin2_b = (const float*)d_in[11];
    const float* fc_w   = (const float*)d_in[12];
    const float* fc_b   = (const float*)d_in[13];
    const int* ei       = (const int*)d_in[14];
    const int* batch    = (const int*)d_in[15];

    const int N = in_sizes[0] / XD;
    const int E = in_sizes[1] / ED;
    const int G = out_size / 10;

    float *hP, *tP, *h1P, *plP, *csP, *cqP, *scP, *shP, *esP;
    int *ssrcP, *epermP, *cntP, *rowP, *ofsP;
    cudaGetSymbolAddress((void**)&hP,    g_h);
    cudaGetSymbolAddress((void**)&tP,    g_t);
    cudaGetSymbolAddress((void**)&h1P,   g_h1);
    cudaGetSymbolAddress((void**)&plP,   g_pooled);
    cudaGetSymbolAddress((void**)&csP,   g_colsum);
    cudaGetSymbolAddress((void**)&cqP,   g_colsumsq);
    cudaGetSymbolAddress((void**)&scP,   g_scale);
    cudaGetSymbolAddress((void**)&shP,   g_shift);
    cudaGetSymbolAddress((void**)&esP,   g_esort);
    cudaGetSymbolAddress((void**)&ssrcP, g_ssrc);
    cudaGetSymbolAddress((void**)&epermP,g_eperm);
    cudaGetSymbolAddress((void**)&cntP,  g_cnt);
    cudaGetSymbolAddress((void**)&rowP,  g_row);
    cudaGetSymbolAddress((void**)&ofsP,  g_ofs);

    const int gemmGrid = (N + 127) / 128;

    // ---- CSR build + edge-MLP precompute (ONCE; reused by all 3 layers) ----
    cudaMemsetAsync(cntP, 0, N * sizeof(int));
    hist_kernel<<<(E + 255) / 256, 256>>>(ei, cntP, E);
    prefix_kernel<<<1, 1024>>>(cntP, rowP, ofsP, N, E);
    scatter_kernel<<<(E + 255) / 256, 256>>>(ei, ofsP, ssrcP, epermP, E);
    ecomp_kernel<<<(E * 32 + 255) / 256, 256>>>(ea, epermP, edge_w, edge_b, esP, E);

    // node encoder: h = x @ node_w + node_b
    gemm_k<XD, false, false, false><<<gemmGrid, 256>>>(
        x, node_w, node_b, hP, N, nullptr, nullptr, nullptr, nullptr);

    for (int l = 0; l < 3; l++) {
        // t = h + segment_sum(relu(h[src] + e)); also zeroes BN stat accumulators
        aggr_kernel<<<(N * 32 + 255) / 256, 256>>>(
            hP, tP, esP, ssrcP, rowP, N, csP, cqP);
        // h1 = t @ W1 + b1, with column sum/sumsq accumulation
        gemm_k<H, false, false, true><<<gemmGrid, 256>>>(
            tP, lin1_w + (size_t)l * H * H, lin1_b + l * H, h1P, N,
            nullptr, nullptr, csP, cqP);
        // BN scale/shift
        bn_finalize_kernel<<<1, H>>>(csP, cqP, bn_g + l * H, bn_b + l * H, N, scP, shP);
        // h = relu( relu(bn(h1)) @ W2 + b2 )
        gemm_k<H, true, true, false><<<gemmGrid, 256>>>(
            h1P, lin2_w + (size_t)l * H * H, lin2_b + l * H, hP, N,
            scP, shP, nullptr, nullptr);
    }

    // pooled = segment_sum(h, batch)
    cudaMemsetAsync(plP, 0, (size_t)G * H * sizeof(float));
    int poolWarps = (N + 63) / 64;
    pool_kernel<<<(poolWarps + 7) / 8, 256>>>(hP, batch, plP, N);

    // out = pooled @ fc_w + fc_b
    final_gemm_kernel<<<G, H>>>(plP, fc_w, fc_b, (float*)d_out, G);
}

// round 11
// speedup vs baseline: 1.3991x; 1.1402x over previous
#include <cuda_runtime.h>
#include <cstdint>

#define H   128
#define XD  64
#define ED  16
#define NMAX 50000
#define EMAX 640000
#define GPMAX 512
#define BN_EPS 1e-5f

// ---------------- scratch (static device globals; no allocation) ----------------
__device__ __align__(16) float g_h  [(size_t)NMAX * H];
__device__ __align__(16) float g_t  [(size_t)NMAX * H];
__device__ __align__(16) float g_h1 [(size_t)NMAX * H];
__device__ __align__(16) float g_pooled[GPMAX * H];
__device__ __align__(16) float g_colsum[H];
__device__ __align__(16) float g_colsumsq[H];
__device__ __align__(16) float g_scale[H];
__device__ __align__(16) float g_shift[H];
// edge features precomputed ONCE (layer-invariant), stored dst-sorted
__device__ __align__(16) float g_esort[(size_t)EMAX * H];   // 327 MB
__device__ int   g_ssrc [EMAX];
__device__ int   g_eperm[EMAX];
__device__ int   g_cnt  [NMAX];
__device__ int   g_row  [NMAX + 1];
__device__ int   g_ofs  [NMAX];

// ---------------- helpers ----------------
__device__ __forceinline__ void red_add_v4(float* addr, float4 v) {
    asm volatile("red.global.add.v4.f32 [%0], {%1,%2,%3,%4};"
                 :: "l"(addr), "f"(v.x), "f"(v.y), "f"(v.z), "f"(v.w)
                 : "memory");
}

#define FMA2(acc_, a_, b_) \
    asm("fma.rn.f32x2 %0, %1, %2, %0;" : "+l"(acc_) : "l"(a_), "l"(b_))

// ---------------- CSR build: histogram -> scan -> scatter ----------------
__global__ void hist_kernel(const int* __restrict__ ei, int* __restrict__ cnt, int E)
{
    int e = blockIdx.x * blockDim.x + threadIdx.x;
    if (e < E) atomicAdd(&cnt[__ldg(ei + E + e)], 1);
}

__global__ void prefix_kernel(const int* __restrict__ cnt, int* __restrict__ row_ptr,
                              int* __restrict__ ofs, int N, int E)
{
    __shared__ int ssum[1024];
    int tid = threadIdx.x;
    int per = (N + 1023) >> 10;
    int start = tid * per;
    int end = min(start + per, N);
    int s = 0;
    for (int i = start; i < end; i++) s += cnt[i];
    ssum[tid] = s;
    __syncthreads();
    #pragma unroll
    for (int off = 1; off < 1024; off <<= 1) {
        int v = (tid >= off) ? ssum[tid - off] : 0;
        __syncthreads();
        ssum[tid] += v;
        __syncthreads();
    }
    int run = (tid > 0) ? ssum[tid - 1] : 0;
    for (int i = start; i < end; i++) {
        row_ptr[i] = run;
        ofs[i] = run;
        run += cnt[i];
    }
    if (tid == 0) row_ptr[N] = E;
}

__global__ void scatter_kernel(const int* __restrict__ ei,
                               int* __restrict__ ofs, int* __restrict__ ssrc,
                               int* __restrict__ eperm, int E)
{
    int e = blockIdx.x * blockDim.x + threadIdx.x;
    if (e >= E) return;
    int dst = __ldg(ei + E + e);
    int pos = atomicAdd(&ofs[dst], 1);
    ssrc[pos] = __ldg(ei + e);
    eperm[pos] = e;
}

// ---------------- edge MLP precompute as tiled GEMM (ONCE) ----------------
// esort[pos, :] = ea[eperm[pos], :] @ Ew[16,128] + Eb
// CTA tile: 128 edges x 128 features, K=16. FMA2 microkernel, coalesced stores.
__global__ void __launch_bounds__(256, 2) ecomp_kernel(
    const float* __restrict__ ea, const int* __restrict__ eperm,
    const float* __restrict__ eW, const float* __restrict__ eb,
    float* __restrict__ esort, int E)
{
    __shared__ __align__(16) float As[ED][132];   // k-major gathered A tile
    __shared__ __align__(16) float Bs[ED][128];   // W
    const int tid = threadIdx.x;
    const int tx  = tid & 15;        // 16 col-groups of 8
    const int ty  = tid >> 4;        // 16 row-groups of 8
    const int rowBlk = blockIdx.x * 128;

    // load W (16x128 = 2048 floats): 256 threads x 2 float4
    {
        int idx = tid * 4;          // covers first 1024 floats
        *(float4*)&Bs[idx >> 7][idx & 127] = *(const float4*)(eW + idx);
        idx += 1024;
        *(float4*)&Bs[idx >> 7][idx & 127] = *(const float4*)(eW + idx);
    }
    // gather A tile: each thread loads half an edge row (8 floats)
    {
        int r = tid >> 1;                   // 0..127
        int c0 = (tid & 1) * 8;             // 0 or 8
        int pos = rowBlk + r;
        float4 v0, v1;
        if (pos < E) {
            int e = __ldg(eperm + pos);
            const float4* ap = (const float4*)(ea + (size_t)e * ED + c0);
            v0 = __ldg(ap + 0);
            v1 = __ldg(ap + 1);
        } else {
            v0 = make_float4(0.f, 0.f, 0.f, 0.f);
            v1 = v0;
        }
        As[c0 + 0][r] = v0.x; As[c0 + 1][r] = v0.y;
        As[c0 + 2][r] = v0.z; As[c0 + 3][r] = v0.w;
        As[c0 + 4][r] = v1.x; As[c0 + 5][r] = v1.y;
        As[c0 + 6][r] = v1.z; As[c0 + 7][r] = v1.w;
    }
    __syncthreads();

    unsigned long long accP[8][4];
    #pragma unroll
    for (int r = 0; r < 8; r++)
        #pragma unroll
        for (int c = 0; c < 4; c++) accP[r][c] = 0ull;

    #pragma unroll
    for (int kk = 0; kk < ED; kk++) {
        float4 a0 = *(const float4*)&As[kk][ty * 8];
        float4 a1 = *(const float4*)&As[kk][ty * 8 + 4];
        ulonglong2 bq0 = *(const ulonglong2*)&Bs[kk][tx * 8];
        ulonglong2 bq1 = *(const ulonglong2*)&Bs[kk][tx * 8 + 4];
        unsigned long long bP0 = bq0.x, bP1 = bq0.y, bP2 = bq1.x, bP3 = bq1.y;
        float a[8] = {a0.x, a0.y, a0.z, a0.w, a1.x, a1.y, a1.z, a1.w};
        #pragma unroll
        for (int r = 0; r < 8; r++) {
            unsigned long long aP;
            asm("mov.b64 %0, {%1, %1};" : "=l"(aP) : "f"(a[r]));
            FMA2(accP[r][0], aP, bP0);
            FMA2(accP[r][1], aP, bP1);
            FMA2(accP[r][2], aP, bP2);
            FMA2(accP[r][3], aP, bP3);
        }
    }

    float bias_c[8];
    #pragma unroll
    for (int j = 0; j < 8; j++) bias_c[j] = __ldg(eb + tx * 8 + j);

    #pragma unroll
    for (int r = 0; r < 8; r++) {
        int pos = rowBlk + ty * 8 + r;
        if (pos < E) {
            float o[8];
            #pragma unroll
            for (int c = 0; c < 4; c++) {
                float lo, hi;
                asm("mov.b64 {%0, %1}, %2;" : "=f"(lo), "=f"(hi) : "l"(accP[r][c]));
                o[2 * c]     = lo + bias_c[2 * c];
                o[2 * c + 1] = hi + bias_c[2 * c + 1];
            }
            *(float4*)(esort + (size_t)pos * H + tx * 8)     = make_float4(o[0], o[1], o[2], o[3]);
            *(float4*)(esort + (size_t)pos * H + tx * 8 + 4) = make_float4(o[4], o[5], o[6], o[7]);
        }
    }
}

// ------- aggregation (per layer): t[n] = h[n] + sum_{pos in row n} relu(h[ssrc[pos]] + esort[pos]) ------
__global__ void __launch_bounds__(256) aggr_kernel(
    const float* __restrict__ h, float* __restrict__ t,
    const float* __restrict__ esort, const int* __restrict__ ssrc,
    const int* __restrict__ row_ptr, int N,
    float* __restrict__ cs, float* __restrict__ cq)
{
    if (blockIdx.x == 0 && threadIdx.x < H) { cs[threadIdx.x] = 0.f; cq[threadIdx.x] = 0.f; }

    const int lane = threadIdx.x & 31;
    const int f = lane * 4;
    int n = (blockIdx.x * blockDim.x + threadIdx.x) >> 5;
    if (n >= N) return;

    int beg = __ldg(row_ptr + n);
    int end = __ldg(row_ptr + n + 1);
    float4 acc = *(const float4*)(h + (size_t)n * H + f);   // self term (eps=0)

    int pos = beg;
    for (; pos + 2 <= end; pos += 2) {
        int s0 = __ldg(ssrc + pos);
        int s1 = __ldg(ssrc + pos + 1);
        float4 e0 = *(const float4*)(esort + (size_t)pos * H + f);
        float4 e1 = *(const float4*)(esort + (size_t)(pos + 1) * H + f);
        float4 h0 = *(const float4*)(h + (size_t)s0 * H + f);
        float4 h1 = *(const float4*)(h + (size_t)s1 * H + f);
        acc.x += fmaxf(h0.x + e0.x, 0.f) + fmaxf(h1.x + e1.x, 0.f);
        acc.y += fmaxf(h0.y + e0.y, 0.f) + fmaxf(h1.y + e1.y, 0.f);
        acc.z += fmaxf(h0.z + e0.z, 0.f) + fmaxf(h1.z + e1.z, 0.f);
        acc.w += fmaxf(h0.w + e0.w, 0.f) + fmaxf(h1.w + e1.w, 0.f);
    }
    if (pos < end) {
        int s0 = __ldg(ssrc + pos);
        float4 e0 = *(const float4*)(esort + (size_t)pos * H + f);
        float4 h0 = *(const float4*)(h + (size_t)s0 * H + f);
        acc.x += fmaxf(h0.x + e0.x, 0.f);
        acc.y += fmaxf(h0.y + e0.y, 0.f);
        acc.z += fmaxf(h0.z + e0.z, 0.f);
        acc.w += fmaxf(h0.w + e0.w, 0.f);
    }
    *(float4*)(t + (size_t)n * H + f) = acc;
}

// ---------------- tiled SGEMM with packed f32x2 FMA ----------------
template<int K, bool BN_IN, bool RELU_OUT, bool STATS>
__global__ void __launch_bounds__(256, 2) gemm_k(
    const float* __restrict__ A, const float* __restrict__ W,
    const float* __restrict__ bias, float* __restrict__ C, int M,
    const float* __restrict__ bscale, const float* __restrict__ bshift,
    float* __restrict__ gsum, float* __restrict__ gsq)
{
    constexpr int NT = K / 8;
    __shared__ __align__(16) float As[2][8][132];
    __shared__ __align__(16) float Bs[2][8][128];
    __shared__ float s_sum[128];
    __shared__ float s_sq[128];

    const int tid = threadIdx.x;
    const int tx  = tid & 15;
    const int ty  = tid >> 4;
    const int rowBlk = blockIdx.x * 128;

    if (STATS && tid < 128) { s_sum[tid] = 0.f; s_sq[tid] = 0.f; }

    const int aRow = tid >> 1;
    const int aK   = (tid & 1) << 2;
    const int wK   = tid >> 5;
    const int wN   = (tid & 31) << 2;

    unsigned long long accP[8][4];
    #pragma unroll
    for (int r = 0; r < 8; r++)
        #pragma unroll
        for (int c = 0; c < 4; c++) accP[r][c] = 0ull;

    float4 va, vb;
    {
        int grow = rowBlk + aRow;
        if (grow < M) {
            va = *(const float4*)(A + (size_t)grow * K + aK);
            if (BN_IN) {
                int kb = aK;
                va.x = fmaxf(va.x * __ldg(bscale + kb + 0) + __ldg(bshift + kb + 0), 0.f);
                va.y = fmaxf(va.y * __ldg(bscale + kb + 1) + __ldg(bshift + kb + 1), 0.f);
                va.z = fmaxf(va.z * __ldg(bscale + kb + 2) + __ldg(bshift + kb + 2), 0.f);
                va.w = fmaxf(va.w * __ldg(bscale + kb + 3) + __ldg(bshift + kb + 3), 0.f);
            }
        } else va = make_float4(0.f, 0.f, 0.f, 0.f);
        vb = *(const float4*)(W + (size_t)wK * 128 + wN);
    }
    As[0][aK + 0][aRow] = va.x;
    As[0][aK + 1][aRow] = va.y;
    As[0][aK + 2][aRow] = va.z;
    As[0][aK + 3][aRow] = va.w;
    *(float4*)&Bs[0][wK][wN] = vb;
    __syncthreads();

    for (int kt = 0; kt < NT; kt++) {
        const int cur = kt & 1;
        if (kt + 1 < NT) {
            int gk = (kt + 1) * 8;
            int grow = rowBlk + aRow;
            if (grow < M) {
                va = *(const float4*)(A + (size_t)grow * K + gk + aK);
                if (BN_IN) {
                    int kb = gk + aK;
                    va.x = fmaxf(va.x * __ldg(bscale + kb + 0) + __ldg(bshift + kb + 0), 0.f);
                    va.y = fmaxf(va.y * __ldg(bscale + kb + 1) + __ldg(bshift + kb + 1), 0.f);
                    va.z = fmaxf(va.z * __ldg(bscale + kb + 2) + __ldg(bshift + kb + 2), 0.f);
                    va.w = fmaxf(va.w * __ldg(bscale + kb + 3) + __ldg(bshift + kb + 3), 0.f);
                }
            } else va = make_float4(0.f, 0.f, 0.f, 0.f);
            vb = *(const float4*)(W + (size_t)(gk + wK) * 128 + wN);
        }
        #pragma unroll
        for (int kk = 0; kk < 8; kk++) {
            float4 a0 = *(const float4*)&As[cur][kk][ty * 8];
            float4 a1 = *(const float4*)&As[cur][kk][ty * 8 + 4];
            ulonglong2 bq0 = *(const ulonglong2*)&Bs[cur][kk][tx * 8];
            ulonglong2 bq1 = *(const ulonglong2*)&Bs[cur][kk][tx * 8 + 4];
            unsigned long long bP0 = bq0.x, bP1 = bq0.y, bP2 = bq1.x, bP3 = bq1.y;
            float a[8] = {a0.x, a0.y, a0.z, a0.w, a1.x, a1.y, a1.z, a1.w};
            #pragma unroll
            for (int r = 0; r < 8; r++) {
                unsigned long long aP;
                asm("mov.b64 %0, {%1, %1};" : "=l"(aP) : "f"(a[r]));
                FMA2(accP[r][0], aP, bP0);
                FMA2(accP[r][1], aP, bP1);
                FMA2(accP[r][2], aP, bP2);
                FMA2(accP[r][3], aP, bP3);
            }
        }
        if (kt + 1 < NT) {
            const int nxt = cur ^ 1;
            As[nxt][aK + 0][aRow] = va.x;
            As[nxt][aK + 1][aRow] = va.y;
            As[nxt][aK + 2][aRow] = va.z;
            As[nxt][aK + 3][aRow] = va.w;
            *(float4*)&Bs[nxt][wK][wN] = vb;
        }
        __syncthreads();
    }

    float bias_c[8];
    #pragma unroll
    for (int j = 0; j < 8; j++) bias_c[j] = __ldg(bias + tx * 8 + j);

    float ps[8], pq[8];
    if (STATS) {
        #pragma unroll
        for (int j = 0; j < 8; j++) { ps[j] = 0.f; pq[j] = 0.f; }
    }

    #pragma unroll
    for (int r = 0; r < 8; r++) {
        int grow = rowBlk + ty * 8 + r;
        if (grow < M) {
            float o[8];
            #pragma unroll
            for (int c = 0; c < 4; c++) {
                float lo, hi;
                asm("mov.b64 {%0, %1}, %2;" : "=f"(lo), "=f"(hi) : "l"(accP[r][c]));
                o[2 * c]     = lo;
                o[2 * c + 1] = hi;
            }
            #pragma unroll
            for (int j = 0; j < 8; j++) {
                float v = o[j] + bias_c[j];
                if (STATS) { ps[j] += v; pq[j] += v * v; }
                if (RELU_OUT) v = fmaxf(v, 0.f);
                o[j] = v;
            }
            *(float4*)(C + (size_t)grow * 128 + tx * 8)     = make_float4(o[0], o[1], o[2], o[3]);
            *(float4*)(C + (size_t)grow * 128 + tx * 8 + 4) = make_float4(o[4], o[5], o[6], o[7]);
        }
    }

    if (STATS) {
        #pragma unroll
        for (int j = 0; j < 8; j++) {
            atomicAdd(&s_sum[tx * 8 + j], ps[j]);
            atomicAdd(&s_sq [tx * 8 + j], pq[j]);
        }
        __syncthreads();
        if (tid < 128) {
            atomicAdd(gsum + tid, s_sum[tid]);
            atomicAdd(gsq  + tid, s_sq[tid]);
        }
    }
}

// ---------------- BN finalize ----------------
__global__ void bn_finalize_kernel(const float* __restrict__ cs, const float* __restrict__ cq,
                                   const float* __restrict__ g, const float* __restrict__ b,
                                   int N, float* __restrict__ scale, float* __restrict__ shift)
{
    int j = threadIdx.x;
    float invN = 1.f / (float)N;
    float mean = cs[j] * invN;
    float var  = cq[j] * invN - mean * mean;
    float inv  = rsqrtf(var + BN_EPS);
    float sc   = g[j] * inv;
    scale[j] = sc;
    shift[j] = b[j] - mean * sc;
}

// ---------------- global add pool ----------------
__global__ void __launch_bounds__(256) pool_kernel(
    const float* __restrict__ h, const int* __restrict__ batch,
    float* __restrict__ pooled, int N)
{
    const int lane = threadIdx.x & 31;
    const int warp = (blockIdx.x * blockDim.x + threadIdx.x) >> 5;
    const int CHUNK = 64;
    int n0 = warp * CHUNK;
    if (n0 >= N) return;
    int n1 = n0 + CHUNK; if (n1 > N) n1 = N;
    const int f = lane * 4;

    int cur = __ldg(batch + n0);
    float4 acc = make_float4(0.f, 0.f, 0.f, 0.f);
    for (int n = n0; n < n1; n++) {
        int b = __ldg(batch + n);
        if (b != cur) {
            red_add_v4(pooled + (size_t)cur * H + f, acc);
            acc = make_float4(0.f, 0.f, 0.f, 0.f);
            cur = b;
        }
        float4 v = *(const float4*)(h + (size_t)n * H + f);
        acc.x += v.x; acc.y += v.y; acc.z += v.z; acc.w += v.w;
    }
    red_add_v4(pooled + (size_t)cur * H + f, acc);
}

// ---------------- final FC ----------------
__global__ void final_gemm_kernel(const float* __restrict__ pooled,
                                  const float* __restrict__ fcw, const float* __restrict__ fcb,
                                  float* __restrict__ out, int G)
{
    __shared__ float row[H];
    int g = blockIdx.x;
    row[threadIdx.x] = pooled[(size_t)g * H + threadIdx.x];
    __syncthreads();
    if (threadIdx.x < 10) {
        float acc = fcb[threadIdx.x];
        #pragma unroll 8
        for (int k = 0; k < H; k++)
            acc += row[k] * fcw[k * 10 + threadIdx.x];
        out[g * 10 + threadIdx.x] = acc;
    }
}

// ---------------- launch ----------------
extern "C" void kernel_launch(void* const* d_in, const int* in_sizes, int n_in,
                              void* d_out, int out_size)
{
    const float* x      = (const float*)d_in[0];
    const float* ea     = (const float*)d_in[1];
    const float* node_w = (const float*)d_in[2];
    const float* node_b = (const float*)d_in[3];
    const float* edge_w = (const float*)d_in[4];
    const float* edge_b = (const float*)d_in[5];
    const float* lin1_w = (const float*)d_in[6];
    const float* lin1_b = (const float*)d_in[7];
    const float* bn_g   = (const float*)d_in[8];
    const float* bn_b   = (const float*)d_in[9];
    const float* lin2_w = (const float*)d_in[10];
    const float* lin2_b = (const float*)d_in[11];
    const float* fc_w   = (const float*)d_in[12];
    const float* fc_b   = (const float*)d_in[13];
    const int* ei       = (const int*)d_in[14];
    const int* batch    = (const int*)d_in[15];

    const int N = in_sizes[0] / XD;
    const int E = in_sizes[1] / ED;
    const int G = out_size / 10;

    float *hP, *tP, *h1P, *plP, *csP, *cqP, *scP, *shP, *esP;
    int *ssrcP, *epermP, *cntP, *rowP, *ofsP;
    cudaGetSymbolAddress((void**)&hP,    g_h);
    cudaGetSymbolAddress((void**)&tP,    g_t);
    cudaGetSymbolAddress((void**)&h1P,   g_h1);
    cudaGetSymbolAddress((void**)&plP,   g_pooled);
    cudaGetSymbolAddress((void**)&csP,   g_colsum);
    cudaGetSymbolAddress((void**)&cqP,   g_colsumsq);
    cudaGetSymbolAddress((void**)&scP,   g_scale);
    cudaGetSymbolAddress((void**)&shP,   g_shift);
    cudaGetSymbolAddress((void**)&esP,   g_esort);
    cudaGetSymbolAddress((void**)&ssrcP, g_ssrc);
    cudaGetSymbolAddress((void**)&epermP,g_eperm);
    cudaGetSymbolAddress((void**)&cntP,  g_cnt);
    cudaGetSymbolAddress((void**)&rowP,  g_row);
    cudaGetSymbolAddress((void**)&ofsP,  g_ofs);

    const int gemmGrid = (N + 127) / 128;

    // ---- CSR build + edge-MLP precompute (ONCE; reused by all 3 layers) ----
    cudaMemsetAsync(cntP, 0, N * sizeof(int));
    hist_kernel<<<(E + 255) / 256, 256>>>(ei, cntP, E);
    prefix_kernel<<<1, 1024>>>(cntP, rowP, ofsP, N, E);
    scatter_kernel<<<(E + 255) / 256, 256>>>(ei, ofsP, ssrcP, epermP, E);
    ecomp_kernel<<<(E + 127) / 128, 256>>>(ea, epermP, edge_w, edge_b, esP, E);

    // node encoder: h = x @ node_w + node_b
    gemm_k<XD, false, false, false><<<gemmGrid, 256>>>(
        x, node_w, node_b, hP, N, nullptr, nullptr, nullptr, nullptr);

    for (int l = 0; l < 3; l++) {
        // t = h + segment_sum(relu(h[src] + e)); also zeroes BN stat accumulators
        aggr_kernel<<<(N * 32 + 255) / 256, 256>>>(
            hP, tP, esP, ssrcP, rowP, N, csP, cqP);
        // h1 = t @ W1 + b1, with column sum/sumsq accumulation
        gemm_k<H, false, false, true><<<gemmGrid, 256>>>(
            tP, lin1_w + (size_t)l * H * H, lin1_b + l * H, h1P, N,
            nullptr, nullptr, csP, cqP);
        // BN scale/shift
        bn_finalize_kernel<<<1, H>>>(csP, cqP, bn_g + l * H, bn_b + l * H, N, scP, shP);
        // h = relu( relu(bn(h1)) @ W2 + b2 )
        gemm_k<H, true, true, false><<<gemmGrid, 256>>>(
            h1P, lin2_w + (size_t)l * H * H, lin2_b + l * H, hP, N,
            scP, shP, nullptr, nullptr);
    }

    // pooled = segment_sum(h, batch)
    cudaMemsetAsync(plP, 0, (size_t)G * H * sizeof(float));
    int poolWarps = (N + 63) / 64;
    pool_kernel<<<(poolWarps + 7) / 8, 256>>>(hP, batch, plP, N);

    // out = pooled @ fc_w + fc_b
    final_gemm_kernel<<<G, H>>>(plP, fc_w, fc_b, (float*)d_out, G);
}

// round 12
// speedup vs baseline: 1.6037x; 1.1462x over previous
#include <cuda_runtime.h>
#include <cuda_fp16.h>
#include <cstdint>

#define H   128
#define XD  64
#define ED  16
#define NMAX 50000
#define EMAX 640000
#define GPMAX 512
#define BN_EPS 1e-5f

// ---------------- scratch (static device globals; no allocation) ----------------
__device__ __align__(16) float g_h  [(size_t)NMAX * H];
__device__ __align__(16) float g_t  [(size_t)NMAX * H];
__device__ __align__(16) float g_h1 [(size_t)NMAX * H];
__device__ __align__(16) float g_pooled[GPMAX * H];
__device__ __align__(16) float g_colsum[H];
__device__ __align__(16) float g_colsumsq[H];
__device__ __align__(16) float g_scale[H];
__device__ __align__(16) float g_shift[H];
// edge features precomputed ONCE (layer-invariant), dst-sorted, fp16 (halves HBM traffic)
__device__ __align__(16) __half g_esort[(size_t)EMAX * H];   // 164 MB
__device__ int   g_ssrc [EMAX];
__device__ int   g_eperm[EMAX];
__device__ int   g_cnt  [NMAX];
__device__ int   g_row  [NMAX + 1];
__device__ int   g_ofs  [NMAX];

// ---------------- helpers ----------------
__device__ __forceinline__ void red_add_v4(float* addr, float4 v) {
    asm volatile("red.global.add.v4.f32 [%0], {%1,%2,%3,%4};"
                 :: "l"(addr), "f"(v.x), "f"(v.y), "f"(v.z), "f"(v.w)
                 : "memory");
}

#define FMA2(acc_, a_, b_) \
    asm("fma.rn.f32x2 %0, %1, %2, %0;" : "+l"(acc_) : "l"(a_), "l"(b_))

// ---------------- CSR build: histogram -> scan -> scatter ----------------
__global__ void hist_kernel(const int* __restrict__ ei, int* __restrict__ cnt, int E)
{
    int e = blockIdx.x * blockDim.x + threadIdx.x;
    if (e < E) atomicAdd(&cnt[__ldg(ei + E + e)], 1);
}

__global__ void prefix_kernel(const int* __restrict__ cnt, int* __restrict__ row_ptr,
                              int* __restrict__ ofs, int N, int E)
{
    __shared__ int ssum[1024];
    int tid = threadIdx.x;
    int per = (N + 1023) >> 10;
    int start = tid * per;
    int end = min(start + per, N);
    int s = 0;
    for (int i = start; i < end; i++) s += cnt[i];
    ssum[tid] = s;
    __syncthreads();
    #pragma unroll
    for (int off = 1; off < 1024; off <<= 1) {
        int v = (tid >= off) ? ssum[tid - off] : 0;
        __syncthreads();
        ssum[tid] += v;
        __syncthreads();
    }
    int run = (tid > 0) ? ssum[tid - 1] : 0;
    for (int i = start; i < end; i++) {
        row_ptr[i] = run;
        ofs[i] = run;
        run += cnt[i];
    }
    if (tid == 0) row_ptr[N] = E;
}

__global__ void scatter_kernel(const int* __restrict__ ei,
                               int* __restrict__ ofs, int* __restrict__ ssrc,
                               int* __restrict__ eperm, int E)
{
    int e = blockIdx.x * blockDim.x + threadIdx.x;
    if (e >= E) return;
    int dst = __ldg(ei + E + e);
    int pos = atomicAdd(&ofs[dst], 1);
    ssrc[pos] = __ldg(ei + e);
    eperm[pos] = e;
}

// ---------------- edge MLP precompute as tiled GEMM (ONCE), fp16 output ----------------
// esort[pos, :] = half( ea[eperm[pos], :] @ Ew[16,128] + Eb )
__global__ void __launch_bounds__(256, 2) ecomp_kernel(
    const float* __restrict__ ea, const int* __restrict__ eperm,
    const float* __restrict__ eW, const float* __restrict__ eb,
    __half* __restrict__ esort, int E)
{
    __shared__ __align__(16) float As[ED][132];   // k-major gathered A tile
    __shared__ __align__(16) float Bs[ED][128];   // W
    const int tid = threadIdx.x;
    const int tx  = tid & 15;        // 16 col-groups of 8
    const int ty  = tid >> 4;        // 16 row-groups of 8
    const int rowBlk = blockIdx.x * 128;

    // load W (16x128 = 2048 floats): 256 threads x 2 float4
    {
        int idx = tid * 4;
        *(float4*)&Bs[idx >> 7][idx & 127] = *(const float4*)(eW + idx);
        idx += 1024;
        *(float4*)&Bs[idx >> 7][idx & 127] = *(const float4*)(eW + idx);
    }
    // gather A tile: each thread loads half an edge row (8 floats)
    {
        int r = tid >> 1;
        int c0 = (tid & 1) * 8;
        int pos = rowBlk + r;
        float4 v0, v1;
        if (pos < E) {
            int e = __ldg(eperm + pos);
            const float4* ap = (const float4*)(ea + (size_t)e * ED + c0);
            v0 = __ldg(ap + 0);
            v1 = __ldg(ap + 1);
        } else {
            v0 = make_float4(0.f, 0.f, 0.f, 0.f);
            v1 = v0;
        }
        As[c0 + 0][r] = v0.x; As[c0 + 1][r] = v0.y;
        As[c0 + 2][r] = v0.z; As[c0 + 3][r] = v0.w;
        As[c0 + 4][r] = v1.x; As[c0 + 5][r] = v1.y;
        As[c0 + 6][r] = v1.z; As[c0 + 7][r] = v1.w;
    }
    __syncthreads();

    unsigned long long accP[8][4];
    #pragma unroll
    for (int r = 0; r < 8; r++)
        #pragma unroll
        for (int c = 0; c < 4; c++) accP[r][c] = 0ull;

    #pragma unroll
    for (int kk = 0; kk < ED; kk++) {
        float4 a0 = *(const float4*)&As[kk][ty * 8];
        float4 a1 = *(const float4*)&As[kk][ty * 8 + 4];
        ulonglong2 bq0 = *(const ulonglong2*)&Bs[kk][tx * 8];
        ulonglong2 bq1 = *(const ulonglong2*)&Bs[kk][tx * 8 + 4];
        unsigned long long bP0 = bq0.x, bP1 = bq0.y, bP2 = bq1.x, bP3 = bq1.y;
        float a[8] = {a0.x, a0.y, a0.z, a0.w, a1.x, a1.y, a1.z, a1.w};
        #pragma unroll
        for (int r = 0; r < 8; r++) {
            unsigned long long aP;
            asm("mov.b64 %0, {%1, %1};" : "=l"(aP) : "f"(a[r]));
            FMA2(accP[r][0], aP, bP0);
            FMA2(accP[r][1], aP, bP1);
            FMA2(accP[r][2], aP, bP2);
            FMA2(accP[r][3], aP, bP3);
        }
    }

    float bias_c[8];
    #pragma unroll
    for (int j = 0; j < 8; j++) bias_c[j] = __ldg(eb + tx * 8 + j);

    #pragma unroll
    for (int r = 0; r < 8; r++) {
        int pos = rowBlk + ty * 8 + r;
        if (pos < E) {
            float o[8];
            #pragma unroll
            for (int c = 0; c < 4; c++) {
                float lo, hi;
                asm("mov.b64 {%0, %1}, %2;" : "=f"(lo), "=f"(hi) : "l"(accP[r][c]));
                o[2 * c]     = lo + bias_c[2 * c];
                o[2 * c + 1] = hi + bias_c[2 * c + 1];
            }
            // pack 8 floats -> 8 halves (16 bytes), one store
            __half2 p0 = __floats2half2_rn(o[0], o[1]);
            __half2 p1 = __floats2half2_rn(o[2], o[3]);
            __half2 p2 = __floats2half2_rn(o[4], o[5]);
            __half2 p3 = __floats2half2_rn(o[6], o[7]);
            uint4 pk;
            pk.x = *(unsigned*)&p0; pk.y = *(unsigned*)&p1;
            pk.z = *(unsigned*)&p2; pk.w = *(unsigned*)&p3;
            *(uint4*)(esort + (size_t)pos * H + tx * 8) = pk;
        }
    }
}

// ------- aggregation (per layer): t[n] = h[n] + sum_{pos in row n} relu(h[ssrc[pos]] + esort[pos]) ------
__global__ void __launch_bounds__(256) aggr_kernel(
    const float* __restrict__ h, float* __restrict__ t,
    const __half* __restrict__ esort, const int* __restrict__ ssrc,
    const int* __restrict__ row_ptr, int N,
    float* __restrict__ cs, float* __restrict__ cq)
{
    if (blockIdx.x == 0 && threadIdx.x < H) { cs[threadIdx.x] = 0.f; cq[threadIdx.x] = 0.f; }

    const int lane = threadIdx.x & 31;
    const int f = lane * 4;
    int n = (blockIdx.x * blockDim.x + threadIdx.x) >> 5;
    if (n >= N) return;

    int beg = __ldg(row_ptr + n);
    int end = __ldg(row_ptr + n + 1);
    float4 acc = *(const float4*)(h + (size_t)n * H + f);   // self term (eps=0)

    int pos = beg;
    for (; pos + 2 <= end; pos += 2) {
        int s0 = __ldg(ssrc + pos);
        int s1 = __ldg(ssrc + pos + 1);
        uint2 er0 = __ldg((const uint2*)(esort + (size_t)pos * H + f));
        uint2 er1 = __ldg((const uint2*)(esort + (size_t)(pos + 1) * H + f));
        float4 h0 = *(const float4*)(h + (size_t)s0 * H + f);
        float4 h1 = *(const float4*)(h + (size_t)s1 * H + f);
        float2 e0a = __half22float2(*(const __half2*)&er0.x);
        float2 e0b = __half22float2(*(const __half2*)&er0.y);
        float2 e1a = __half22float2(*(const __half2*)&er1.x);
        float2 e1b = __half22float2(*(const __half2*)&er1.y);
        acc.x += fmaxf(h0.x + e0a.x, 0.f) + fmaxf(h1.x + e1a.x, 0.f);
        acc.y += fmaxf(h0.y + e0a.y, 0.f) + fmaxf(h1.y + e1a.y, 0.f);
        acc.z += fmaxf(h0.z + e0b.x, 0.f) + fmaxf(h1.z + e1b.x, 0.f);
        acc.w += fmaxf(h0.w + e0b.y, 0.f) + fmaxf(h1.w + e1b.y, 0.f);
    }
    if (pos < end) {
        int s0 = __ldg(ssrc + pos);
        uint2 er0 = __ldg((const uint2*)(esort + (size_t)pos * H + f));
        float4 h0 = *(const float4*)(h + (size_t)s0 * H + f);
        float2 e0a = __half22float2(*(const __half2*)&er0.x);
        float2 e0b = __half22float2(*(const __half2*)&er0.y);
        acc.x += fmaxf(h0.x + e0a.x, 0.f);
        acc.y += fmaxf(h0.y + e0a.y, 0.f);
        acc.z += fmaxf(h0.z + e0b.x, 0.f);
        acc.w += fmaxf(h0.w + e0b.y, 0.f);
    }
    *(float4*)(t + (size_t)n * H + f) = acc;
}

// ---------------- tiled SGEMM with packed f32x2 FMA ----------------
template<int K, bool BN_IN, bool RELU_OUT, bool STATS>
__global__ void __launch_bounds__(256, 2) gemm_k(
    const float* __restrict__ A, const float* __restrict__ W,
    const float* __restrict__ bias, float* __restrict__ C, int M,
    const float* __restrict__ bscale, const float* __restrict__ bshift,
    float* __restrict__ gsum, float* __restrict__ gsq)
{
    constexpr int NT = K / 8;
    __shared__ __align__(16) float As[2][8][132];
    __shared__ __align__(16) float Bs[2][8][128];
    __shared__ float s_sum[128];
    __shared__ float s_sq[128];

    const int tid = threadIdx.x;
    const int tx  = tid & 15;
    const int ty  = tid >> 4;
    const int rowBlk = blockIdx.x * 128;

    if (STATS && tid < 128) { s_sum[tid] = 0.f; s_sq[tid] = 0.f; }

    const int aRow = tid >> 1;
    const int aK   = (tid & 1) << 2;
    const int wK   = tid >> 5;
    const int wN   = (tid & 31) << 2;

    unsigned long long accP[8][4];
    #pragma unroll
    for (int r = 0; r < 8; r++)
        #pragma unroll
        for (int c = 0; c < 4; c++) accP[r][c] = 0ull;

    float4 va, vb;
    {
        int grow = rowBlk + aRow;
        if (grow < M) {
            va = *(const float4*)(A + (size_t)grow * K + aK);
            if (BN_IN) {
                int kb = aK;
                va.x = fmaxf(va.x * __ldg(bscale + kb + 0) + __ldg(bshift + kb + 0), 0.f);
                va.y = fmaxf(va.y * __ldg(bscale + kb + 1) + __ldg(bshift + kb + 1), 0.f);
                va.z = fmaxf(va.z * __ldg(bscale + kb + 2) + __ldg(bshift + kb + 2), 0.f);
                va.w = fmaxf(va.w * __ldg(bscale + kb + 3) + __ldg(bshift + kb + 3), 0.f);
            }
        } else va = make_float4(0.f, 0.f, 0.f, 0.f);
        vb = *(const float4*)(W + (size_t)wK * 128 + wN);
    }
    As[0][aK + 0][aRow] = va.x;
    As[0][aK + 1][aRow] = va.y;
    As[0][aK + 2][aRow] = va.z;
    As[0][aK + 3][aRow] = va.w;
    *(float4*)&Bs[0][wK][wN] = vb;
    __syncthreads();

    for (int kt = 0; kt < NT; kt++) {
        const int cur = kt & 1;
        if (kt + 1 < NT) {
            int gk = (kt + 1) * 8;
            int grow = rowBlk + aRow;
            if (grow < M) {
                va = *(const float4*)(A + (size_t)grow * K + gk + aK);
                if (BN_IN) {
                    int kb = gk + aK;
                    va.x = fmaxf(va.x * __ldg(bscale + kb + 0) + __ldg(bshift + kb + 0), 0.f);
                    va.y = fmaxf(va.y * __ldg(bscale + kb + 1) + __ldg(bshift + kb + 1), 0.f);
                    va.z = fmaxf(va.z * __ldg(bscale + kb + 2) + __ldg(bshift + kb + 2), 0.f);
                    va.w = fmaxf(va.w * __ldg(bscale + kb + 3) + __ldg(bshift + kb + 3), 0.f);
                }
            } else va = make_float4(0.f, 0.f, 0.f, 0.f);
            vb = *(const float4*)(W + (size_t)(gk + wK) * 128 + wN);
        }
        #pragma unroll
        for (int kk = 0; kk < 8; kk++) {
            float4 a0 = *(const float4*)&As[cur][kk][ty * 8];
            float4 a1 = *(const float4*)&As[cur][kk][ty * 8 + 4];
            ulonglong2 bq0 = *(const ulonglong2*)&Bs[cur][kk][tx * 8];
            ulonglong2 bq1 = *(const ulonglong2*)&Bs[cur][kk][tx * 8 + 4];
            unsigned long long bP0 = bq0.x, bP1 = bq0.y, bP2 = bq1.x, bP3 = bq1.y;
            float a[8] = {a0.x, a0.y, a0.z, a0.w, a1.x, a1.y, a1.z, a1.w};
            #pragma unroll
            for (int r = 0; r < 8; r++) {
                unsigned long long aP;
                asm("mov.b64 %0, {%1, %1};" : "=l"(aP) : "f"(a[r]));
                FMA2(accP[r][0], aP, bP0);
                FMA2(accP[r][1], aP, bP1);
                FMA2(accP[r][2], aP, bP2);
                FMA2(accP[r][3], aP, bP3);
            }
        }
        if (kt + 1 < NT) {
            const int nxt = cur ^ 1;
            As[nxt][aK + 0][aRow] = va.x;
            As[nxt][aK + 1][aRow] = va.y;
            As[nxt][aK + 2][aRow] = va.z;
            As[nxt][aK + 3][aRow] = va.w;
            *(float4*)&Bs[nxt][wK][wN] = vb;
        }
        __syncthreads();
    }

    float bias_c[8];
    #pragma unroll
    for (int j = 0; j < 8; j++) bias_c[j] = __ldg(bias + tx * 8 + j);

    float ps[8], pq[8];
    if (STATS) {
        #pragma unroll
        for (int j = 0; j < 8; j++) { ps[j] = 0.f; pq[j] = 0.f; }
    }

    #pragma unroll
    for (int r = 0; r < 8; r++) {
        int grow = rowBlk + ty * 8 + r;
        if (grow < M) {
            float o[8];
            #pragma unroll
            for (int c = 0; c < 4; c++) {
                float lo, hi;
                asm("mov.b64 {%0, %1}, %2;" : "=f"(lo), "=f"(hi) : "l"(accP[r][c]));
                o[2 * c]     = lo;
                o[2 * c + 1] = hi;
            }
            #pragma unroll
            for (int j = 0; j < 8; j++) {
                float v = o[j] + bias_c[j];
                if (STATS) { ps[j] += v; pq[j] += v * v; }
                if (RELU_OUT) v = fmaxf(v, 0.f);
                o[j] = v;
            }
            *(float4*)(C + (size_t)grow * 128 + tx * 8)     = make_float4(o[0], o[1], o[2], o[3]);
            *(float4*)(C + (size_t)grow * 128 + tx * 8 + 4) = make_float4(o[4], o[5], o[6], o[7]);
        }
    }

    if (STATS) {
        #pragma unroll
        for (int j = 0; j < 8; j++) {
            atomicAdd(&s_sum[tx * 8 + j], ps[j]);
            atomicAdd(&s_sq [tx * 8 + j], pq[j]);
        }
        __syncthreads();
        if (tid < 128) {
            atomicAdd(gsum + tid, s_sum[tid]);
            atomicAdd(gsq  + tid, s_sq[tid]);
        }
    }
}

// ---------------- BN finalize ----------------
__global__ void bn_finalize_kernel(const float* __restrict__ cs, const float* __restrict__ cq,
                                   const float* __restrict__ g, const float* __restrict__ b,
                                   int N, float* __restrict__ scale, float* __restrict__ shift)
{
    int j = threadIdx.x;
    float invN = 1.f / (float)N;
    float mean = cs[j] * invN;
    float var  = cq[j] * invN - mean * mean;
    float inv  = rsqrtf(var + BN_EPS);
    float sc   = g[j] * inv;
    scale[j] = sc;
    shift[j] = b[j] - mean * sc;
}

// ---------------- global add pool ----------------
__global__ void __launch_bounds__(256) pool_kernel(
    const float* __restrict__ h, const int* __restrict__ batch,
    float* __restrict__ pooled, int N)
{
    const int lane = threadIdx.x & 31;
    const int warp = (blockIdx.x * blockDim.x + threadIdx.x) >> 5;
    const int CHUNK = 64;
    int n0 = warp * CHUNK;
    if (n0 >= N) return;
    int n1 = n0 + CHUNK; if (n1 > N) n1 = N;
    const int f = lane * 4;

    int cur = __ldg(batch + n0);
    float4 acc = make_float4(0.f, 0.f, 0.f, 0.f);
    for (int n = n0; n < n1; n++) {
        int b = __ldg(batch + n);
        if (b != cur) {
            red_add_v4(pooled + (size_t)cur * H + f, acc);
            acc = make_float4(0.f, 0.f, 0.f, 0.f);
            cur = b;
        }
        float4 v = *(const float4*)(h + (size_t)n * H + f);
        acc.x += v.x; acc.y += v.y; acc.z += v.z; acc.w += v.w;
    }
    red_add_v4(pooled + (size_t)cur * H + f, acc);
}

// ---------------- final FC ----------------
__global__ void final_gemm_kernel(const float* __restrict__ pooled,
                                  const float* __restrict__ fcw, const float* __restrict__ fcb,
                                  float* __restrict__ out, int G)
{
    __shared__ float row[H];
    int g = blockIdx.x;
    row[threadIdx.x] = pooled[(size_t)g * H + threadIdx.x];
    __syncthreads();
    if (threadIdx.x < 10) {
        float acc = fcb[threadIdx.x];
        #pragma unroll 8
        for (int k = 0; k < H; k++)
            acc += row[k] * fcw[k * 10 + threadIdx.x];
        out[g * 10 + threadIdx.x] = acc;
    }
}

// ---------------- launch ----------------
extern "C" void kernel_launch(void* const* d_in, const int* in_sizes, int n_in,
                              void* d_out, int out_size)
{
    const float* x      = (const float*)d_in[0];
    const float* ea     = (const float*)d_in[1];
    const float* node_w = (const float*)d_in[2];
    const float* node_b = (const float*)d_in[3];
    const float* edge_w = (const float*)d_in[4];
    const float* edge_b = (const float*)d_in[5];
    const float* lin1_w = (const float*)d_in[6];
    const float* lin1_b = (const float*)d_in[7];
    const float* bn_g   = (const float*)d_in[8];
    const float* bn_b   = (const float*)d_in[9];
    const float* lin2_w = (const float*)d_in[10];
    const float* lin2_b = (const float*)d_in[11];
    const float* fc_w   = (const float*)d_in[12];
    const float* fc_b   = (const float*)d_in[13];
    const int* ei       = (const int*)d_in[14];
    const int* batch    = (const int*)d_in[15];

    const int N = in_sizes[0] / XD;
    const int E = in_sizes[1] / ED;
    const int G = out_size / 10;

    float *hP, *tP, *h1P, *plP, *csP, *cqP, *scP, *shP;
    __half* esP;
    int *ssrcP, *epermP, *cntP, *rowP, *ofsP;
    cudaGetSymbolAddress((void**)&hP,    g_h);
    cudaGetSymbolAddress((void**)&tP,    g_t);
    cudaGetSymbolAddress((void**)&h1P,   g_h1);
    cudaGetSymbolAddress((void**)&plP,   g_pooled);
    cudaGetSymbolAddress((void**)&csP,   g_colsum);
    cudaGetSymbolAddress((void**)&cqP,   g_colsumsq);
    cudaGetSymbolAddress((void**)&scP,   g_scale);
    cudaGetSymbolAddress((void**)&shP,   g_shift);
    cudaGetSymbolAddress((void**)&esP,   g_esort);
    cudaGetSymbolAddress((void**)&ssrcP, g_ssrc);
    cudaGetSymbolAddress((void**)&epermP,g_eperm);
    cudaGetSymbolAddress((void**)&cntP,  g_cnt);
    cudaGetSymbolAddress((void**)&rowP,  g_row);
    cudaGetSymbolAddress((void**)&ofsP,  g_ofs);

    const int gemmGrid = (N + 127) / 128;

    // ---- CSR build + edge-MLP precompute (ONCE; reused by all 3 layers) ----
    cudaMemsetAsync(cntP, 0, N * sizeof(int));
    hist_kernel<<<(E + 255) / 256, 256>>>(ei, cntP, E);
    prefix_kernel<<<1, 1024>>>(cntP, rowP, ofsP, N, E);
    scatter_kernel<<<(E + 255) / 256, 256>>>(ei, ofsP, ssrcP, epermP, E);
    ecomp_kernel<<<(E + 127) / 128, 256>>>(ea, epermP, edge_w, edge_b, esP, E);

    // node encoder: h = x @ node_w + node_b
    gemm_k<XD, false, false, false><<<gemmGrid, 256>>>(
        x, node_w, node_b, hP, N, nullptr, nullptr, nullptr, nullptr);

    for (int l = 0; l < 3; l++) {
        // t = h + segment_sum(relu(h[src] + e)); also zeroes BN stat accumulators
        aggr_kernel<<<(N * 32 + 255) / 256, 256>>>(
            hP, tP, esP, ssrcP, rowP, N, csP, cqP);
        // h1 = t @ W1 + b1, with column sum/sumsq accumulation
        gemm_k<H, false, false, true><<<gemmGrid, 256>>>(
            tP, lin1_w + (size_t)l * H * H, lin1_b + l * H, h1P, N,
            nullptr, nullptr, csP, cqP);
        // BN scale/shift
        bn_finalize_kernel<<<1, H>>>(csP, cqP, bn_g + l * H, bn_b + l * H, N, scP, shP);
        // h = relu( relu(bn(h1)) @ W2 + b2 )
        gemm_k<H, true, true, false><<<gemmGrid, 256>>>(
            h1P, lin2_w + (size_t)l * H * H, lin2_b + l * H, hP, N,
            scP, shP, nullptr, nullptr);
    }

    // pooled = segment_sum(h, batch)
    cudaMemsetAsync(plP, 0, (size_t)G * H * sizeof(float));
    int poolWarps = (N + 63) / 64;
    pool_kernel<<<(poolWarps + 7) / 8, 256>>>(hP, batch, plP, N);

    // out = pooled @ fc_w + fc_b
    final_gemm_kernel<<<G, H>>>(plP, fc_w, fc_b, (float*)d_out, G);
}